// round 9
// baseline (speedup 1.0000x reference)
#include <cuda_runtime.h>
#include <math.h>

// Problem constants
#define H_    112
#define W_    200
#define HW_   (H_*W_)        // 22400
#define C_    64
#define BN_   6
#define PAD_  4
#define HP_   (H_ + 2*PAD_)  // 120
#define WP_   (W_ + 2*PAD_)  // 208
#define HPWP_ (HP_*WP_)      // 24960
#define QW_   208
#define NTAP  81

// tf32 round (rna), b32 destination
__device__ __forceinline__ float tf32r(float x) {
    unsigned u;
    asm("cvt.rna.tf32.f32 %0, %1;" : "=r"(u) : "f"(x));
    return __uint_as_float(u);
}

__device__ __forceinline__ void mma_tf32(float c[4], const float a[4], float b0, float b1) {
    const unsigned* A = (const unsigned*)a;
    asm("mma.sync.aligned.m16n8k8.row.col.f32.tf32.tf32.f32 "
        "{%0,%1,%2,%3}, {%4,%5,%6,%7}, {%8,%9}, {%0,%1,%2,%3};"
        : "+f"(c[0]), "+f"(c[1]), "+f"(c[2]), "+f"(c[3])
        : "r"(A[0]), "r"(A[1]), "r"(A[2]), "r"(A[3]),
          "r"(__float_as_uint(b0)), "r"(__float_as_uint(b1)));
}

// ---------------- scratch -----------------------------------------------------
__device__ float4 g_q   [BN_*H_*QW_*16];  // [n][h][w208][c] channel-last tf32
__device__ float4 g_kpad[BN_*HPWP_*16];   // [n][hp][wp][c] padded channel-last
__device__ float4 g_vpad[BN_*HPWP_*16];
__device__ float4 g_Wf4 [5*8*4*32];       // weight A-fragments: [l][k0][m0][lane]{4}
__device__ float  g_bf  [5*64];           // folded bias

// ---------------- prep: BN fold + weight fragment packing --------------------
__global__ void prep_kernel(const float* __restrict__ wc, const float* __restrict__ gam,
                            const float* __restrict__ bet, const float* __restrict__ mu,
                            const float* __restrict__ var) {
    int idx = blockIdx.x * 256 + threadIdx.x;
    if (idx < 5*8*4*32*4) {
        int l  = idx >> 12;
        int r  = idx & 4095;
        int k0 = r >> 9;
        int r2 = r & 511;
        int m0 = r2 >> 7;
        int r3 = r2 & 127;
        int lane = r3 >> 2;
        int j    = r3 & 3;
        int g  = lane >> 2;
        int tg = lane & 3;
        int o  = m0*16 + g + ((j & 1) ? 8 : 0);
        int ci = k0*8 + tg + ((j >= 2) ? 4 : 0);
        float s = gam[l*64 + o] * rsqrtf(var[l*64 + o] + 1e-5f);
        ((float*)g_Wf4)[idx] = tf32r(s * wc[(l*64 + o)*64 + ci]);
    }
    if (idx < 5*64) {
        float s = gam[idx] * rsqrtf(var[idx] + 1e-5f);
        g_bf[idx] = bet[idx] - s * mu[idx];
    }
}

// ---------------- zero pad borders of K/V and Q column pad -------------------
__global__ void zero_border_kernel() {
    int idx = blockIdx.x * 256 + threadIdx.x;
    const int kvTotal = BN_ * 2560;
    float4 z = make_float4(0.f, 0.f, 0.f, 0.f);
    if (idx < kvTotal) {
        int n = idx / 2560;
        int j = idx - n * 2560;
        int row, col;
        if (j < 1664) {
            int r = j / 208;
            col = j - r * 208;
            row = (r < 4) ? r : (112 + r);
        } else {
            int k = j - 1664;
            row = 4 + (k >> 3);
            int c = k & 7;
            col = (c < 4) ? c : (200 + c);
        }
        size_t base = ((size_t)(n * HP_ + row) * WP_ + col) * 16;
        #pragma unroll
        for (int c4 = 0; c4 < 16; c4++) {
            g_kpad[base + c4] = z;
            g_vpad[base + c4] = z;
        }
    } else if (idx < kvTotal + BN_*H_*8) {
        int qi = idx - kvTotal;
        int n = qi / (H_*8);
        int rr = qi - n*(H_*8);
        int h = rr >> 3;
        int c = rr & 7;
        size_t base = ((size_t)(n*H_ + h)*QW_ + 200 + c) * 16;
        #pragma unroll
        for (int c4 = 0; c4 < 16; c4++) g_q[base + c4] = z;
    }
}

// ---------------- fused 5-layer QKV, single smem buffer per warp -------------
#define XSTRIDE 40
#define BUF_F   (64*XSTRIDE)
#define QKV_SMEM (4*BUF_F*4)    // 40960 B -> 4-5 CTAs/SM

__device__ __forceinline__ void stage_tile(const float* __restrict__ src, float* buf, int lane) {
    int ci0 = lane >> 3;
    int px4 = lane & 7;
    #pragma unroll
    for (int it = 0; it < 16; it++) {
        int ci = it*4 + ci0;
        float4 v = *(const float4*)(src + (size_t)ci*HW_ + px4*4);
        v.x = tf32r(v.x); v.y = tf32r(v.y); v.z = tf32r(v.z); v.w = tf32r(v.w);
        *(float4*)(buf + ci*XSTRIDE + px4*4) = v;
    }
}

__device__ __forceinline__ void layer_mma(const float* buf, int l, int lane, float c[4][4][4]) {
    int g = lane >> 2, tg = lane & 3;
    #pragma unroll
    for (int m = 0; m < 4; m++)
        #pragma unroll
        for (int nt = 0; nt < 4; nt++)
            #pragma unroll
            for (int j = 0; j < 4; j++) c[m][nt][j] = 0.f;

    const float4* wf = g_Wf4 + (size_t)l*8*4*32;
    #pragma unroll
    for (int k0 = 0; k0 < 8; k0++) {
        float4 a[4];
        #pragma unroll
        for (int m = 0; m < 4; m++)
            a[m] = __ldg(wf + (k0*4 + m)*32 + lane);
        #pragma unroll
        for (int nt = 0; nt < 4; nt++) {
            float b0 = buf[(k0*8 + tg)    *XSTRIDE + nt*8 + g];
            float b1 = buf[(k0*8 + tg + 4)*XSTRIDE + nt*8 + g];
            #pragma unroll
            for (int m = 0; m < 4; m++)
                mma_tf32(c[m][nt], (const float*)&a[m], b0, b1);
        }
    }
}

__device__ __forceinline__ void epi_smem(float c[4][4][4], float* bufo, int l, int lane) {
    int g = lane >> 2, tg = lane & 3;
    #pragma unroll
    for (int m = 0; m < 4; m++) {
        float b0 = g_bf[l*64 + m*16 + g];
        float b1 = g_bf[l*64 + m*16 + g + 8];
        #pragma unroll
        for (int nt = 0; nt < 4; nt++) {
            int px = nt*8 + 2*tg;
            bufo[(m*16 + g)    *XSTRIDE + px]     = tf32r(fmaxf(c[m][nt][0] + b0, 0.f));
            bufo[(m*16 + g)    *XSTRIDE + px + 1] = tf32r(fmaxf(c[m][nt][1] + b0, 0.f));
            bufo[(m*16 + g + 8)*XSTRIDE + px]     = tf32r(fmaxf(c[m][nt][2] + b1, 0.f));
            bufo[(m*16 + g + 8)*XSTRIDE + px + 1] = tf32r(fmaxf(c[m][nt][3] + b1, 0.f));
        }
    }
}

__device__ __forceinline__ void epi_gmem(float c[4][4][4], float* base, int l, int lane, int px0) {
    int g = lane >> 2, tg = lane & 3;
    float bs0[4], bs1[4];
    #pragma unroll
    for (int m = 0; m < 4; m++) {
        bs0[m] = g_bf[l*64 + m*16 + g];
        bs1[m] = g_bf[l*64 + m*16 + g + 8];
    }
    #pragma unroll
    for (int nt = 0; nt < 4; nt++) {
        #pragma unroll
        for (int j = 0; j < 2; j++) {
            int px = px0 + nt*8 + 2*tg + j;
            int h = px / W_;
            int w = px - h*W_;
            float* p = base + ((size_t)h*WP_ + w)*64;
            #pragma unroll
            for (int m = 0; m < 4; m++) {
                p[m*16 + g]     = tf32r(fmaxf(c[m][nt][j]     + bs0[m], 0.f));
                p[m*16 + g + 8] = tf32r(fmaxf(c[m][nt][2 + j] + bs1[m], 0.f));
            }
        }
    }
}

__global__ __launch_bounds__(128, 4) void qkv_kernel(const float* __restrict__ img,
                                                     const float* __restrict__ wimg)
{
    extern __shared__ float xs[];
    const int tid = threadIdx.x;
    const int wid = tid >> 5;
    const int lane = tid & 31;
    const int n = blockIdx.y;
    const int px0 = (blockIdx.x*4 + wid) * 32;

    float* bufA = xs + wid * BUF_F;
    float c[4][4][4];

    const float* wsrc = wimg + (size_t)n*C_*HW_ + px0;
    const float* isrc = img  + (size_t)n*C_*HW_ + px0;
    float* qb = (float*)g_q    + (size_t)n*H_*QW_*64;
    float* kb = (float*)g_kpad + (((size_t)n*HP_ + PAD_)*WP_ + PAD_)*64;
    float* vb = (float*)g_vpad + (((size_t)n*HP_ + PAD_)*WP_ + PAD_)*64;

    // warped source -> v (L4), then k (L2 -> in-place -> L3)
    stage_tile(wsrc, bufA, lane);  __syncwarp();
    layer_mma(bufA, 4, lane, c);   epi_gmem(c, vb, 4, lane, px0);
    layer_mma(bufA, 2, lane, c);   __syncwarp();
    epi_smem(c, bufA, 2, lane);    __syncwarp();
    layer_mma(bufA, 3, lane, c);   epi_gmem(c, kb, 3, lane, px0);
    // target source -> q (L0 -> in-place -> L1)
    stage_tile(isrc, bufA, lane);  __syncwarp();
    layer_mma(bufA, 0, lane, c);   __syncwarp();
    epi_smem(c, bufA, 0, lane);    __syncwarp();
    layer_mma(bufA, 1, lane, c);   epi_gmem(c, qb, 1, lane, px0);
}

// ---------------- tensor-core attention, 16-ch passes, 3 CTAs/SM -------------
#define TR_   16
#define TC_   24
#define CPAD4 20                        // 16 ch + 4 pad
#define KV4_F  (TR_*TC_*CPAD4)          // 7680 f = 30720 B
#define SACC_F (8*16*84)                // 10752 f = 43008 B
#define SMEM4_F (KV4_F + SACC_F + 8*16)
#define SMEM4_BYTES (SMEM4_F*4)         // 74240 B -> 3 CTAs/SM

__device__ __forceinline__ void band_store(float* sa, float v, int px, int col,
                                           int di, int acc) {
    int dj = col - px;
    if ((unsigned)dj <= 8u) {
        float* p = sa + px*84 + di*9 + dj;
        if (acc) *p += v; else *p = v;
    }
}

__global__ __launch_bounds__(256, 3) void attn_kernel(float* __restrict__ out)
{
    extern __shared__ float smem[];
    float* kv   = smem;                 // [16 rows][24 cols][20]
    float* sacc = smem + KV4_F;         // [8 warps][16 px][84]
    float* sinv = sacc + SACC_F;        // [8][16]

    const int tid  = threadIdx.x;
    const int wid  = tid >> 5;
    const int lane = tid & 31;
    const int g    = lane >> 2;
    const int tg   = lane & 3;
    const int n  = blockIdx.z;
    const int h0 = blockIdx.y * 8;
    const int w0 = blockIdx.x * 16;
    const int h  = h0 + wid;

    // ---- Q fragments for all 64 channels ----
    float qa[8][4];
    {
        const float* qb = (const float*)g_q + ((size_t)(n*H_ + h)*QW_) * 64;
        #pragma unroll
        for (int k = 0; k < 8; k++) {
            qa[k][0] = qb[(w0 + g)    *64 + k*8 + tg];
            qa[k][1] = qb[(w0 + g + 8)*64 + k*8 + tg];
            qa[k][2] = qb[(w0 + g)    *64 + k*8 + tg + 4];
            qa[k][3] = qb[(w0 + g + 8)*64 + k*8 + tg + 4];
        }
    }

    float* sa = sacc + wid*(16*84);

    // ---- phase 1: similarity, four 16-channel passes, direct band store ----
    #pragma unroll 1
    for (int cp = 0; cp < 4; cp++) {
        __syncthreads();
        {
            const float4* kb = g_kpad + (size_t)(n*HP_ + h0) * WP_ * 16;
            for (int i = tid; i < TR_*TC_*4; i += 256) {
                int px = i >> 2, c4 = i & 3;
                int r = px / TC_, c = px - r*TC_;
                int pcol = w0 + c; if (pcol > 207) pcol = 207;
                float4 v = kb[((size_t)r*WP_ + pcol)*16 + cp*4 + c4];
                *(float4*)(kv + px*CPAD4 + c4*4) = v;
            }
        }
        __syncthreads();
        #pragma unroll 1
        for (int di = 0; di < 9; di++) {
            float c0[3][4];
            #pragma unroll
            for (int nt = 0; nt < 3; nt++)
                #pragma unroll
                for (int j = 0; j < 4; j++) c0[nt][j] = 0.f;
            const float* krow = kv + (wid + di)*(TC_*CPAD4);
            #pragma unroll
            for (int nt = 0; nt < 3; nt++) {
                const float* kc = krow + (nt*8 + g)*CPAD4;
                #pragma unroll
                for (int k = 0; k < 2; k++) {
                    float b0 = kc[k*8 + tg];
                    float b1 = kc[k*8 + tg + 4];
                    mma_tf32(c0[nt], qa[cp*2 + k], b0, b1);
                }
            }
            #pragma unroll
            for (int nt = 0; nt < 3; nt++) {
                int colb = nt*8 + 2*tg;
                band_store(sa, c0[nt][0], g,     colb,     di, cp);
                band_store(sa, c0[nt][1], g,     colb + 1, di, cp);
                band_store(sa, c0[nt][2], g + 8, colb,     di, cp);
                band_store(sa, c0[nt][3], g + 8, colb + 1, di, cp);
            }
        }
    }
    __syncwarp();

    // ---- softmax (2 lanes per px) ----
    {
        int px   = lane & 15;
        int half = lane >> 4;
        float* sp = sa + px*84;
        int t0 = half * 41;
        int tc = 41 - half;
        float mx = -1e30f;
        for (int t = 0; t < tc; t++) {
            float v = sp[t0 + t] * 0.125f;
            mx = fmaxf(mx, v);
        }
        mx = fmaxf(mx, __shfl_xor_sync(0xffffffffu, mx, 16));
        float sum = 0.f;
        for (int t = 0; t < tc; t++) {
            float e = __expf(sp[t0 + t] * 0.125f - mx);
            sum += e;
            sp[t0 + t] = tf32r(e);
        }
        sum += __shfl_xor_sync(0xffffffffu, sum, 16);
        if (half == 0) sinv[wid*16 + px] = 1.f / sum;
    }

    // ---- phase 2: weighting, four 16-channel passes ----
    #pragma unroll 1
    for (int vp = 0; vp < 4; vp++) {
        __syncthreads();
        {
            const float4* vb = g_vpad + (size_t)(n*HP_ + h0) * WP_ * 16;
            for (int i = tid; i < TR_*TC_*4; i += 256) {
                int px = i >> 2, c4 = i & 3;
                int r = px / TC_, c = px - r*TC_;
                int pcol = w0 + c; if (pcol > 207) pcol = 207;
                float4 v = vb[((size_t)r*WP_ + pcol)*16 + vp*4 + c4];
                *(float4*)(kv + px*CPAD4 + c4*4) = v;
            }
        }
        __syncthreads();

        float oc[2][4];
        #pragma unroll
        for (int nt = 0; nt < 2; nt++)
            #pragma unroll
            for (int j = 0; j < 4; j++) oc[nt][j] = 0.f;

        #pragma unroll 1
        for (int di = 0; di < 9; di++) {
            const float* vrow = kv + (wid + di)*(TC_*CPAD4);
            #pragma unroll
            for (int kst = 0; kst < 3; kst++) {
                float bb[2][2];
                #pragma unroll
                for (int nt = 0; nt < 2; nt++) {
                    int i0 = nt*8 + g;
                    int j0 = kst*8 + tg;
                    int dj0 = j0 - i0;
                    int dj1 = dj0 + 4;
                    bb[nt][0] = ((unsigned)dj0 <= 8u) ? sa[i0*84 + di*9 + dj0] : 0.f;
                    bb[nt][1] = ((unsigned)dj1 <= 8u) ? sa[i0*84 + di*9 + dj1] : 0.f;
                }
                float av[4];
                av[0] = vrow[(kst*8 + tg)    *CPAD4 + g];
                av[1] = vrow[(kst*8 + tg)    *CPAD4 + g + 8];
                av[2] = vrow[(kst*8 + tg + 4)*CPAD4 + g];
                av[3] = vrow[(kst*8 + tg + 4)*CPAD4 + g + 8];
                mma_tf32(oc[0], av, bb[0][0], bb[0][1]);
                mma_tf32(oc[1], av, bb[1][0], bb[1][1]);
            }
        }

        // store this pass's 16 channels
        #pragma unroll
        for (int nt = 0; nt < 2; nt++) {
            int pxl = nt*8 + 2*tg;
            float is0 = sinv[wid*16 + pxl];
            float is1 = sinv[wid*16 + pxl + 1];
            int w = w0 + pxl;
            int c = vp*16 + g;
            float* ob0 = out + ((size_t)(n*C_ + c)*H_ + h)*W_;
            float* ob1 = out + ((size_t)(n*C_ + c + 8)*H_ + h)*W_;
            if (w < W_) {
                ob0[w] = oc[nt][0] * is0;
                ob1[w] = oc[nt][2] * is0;
            }
            if (w + 1 < W_) {
                ob0[w+1] = oc[nt][1] * is1;
                ob1[w+1] = oc[nt][3] * is1;
            }
        }
    }
}

// ---------------- launch ------------------------------------------------------
extern "C" void kernel_launch(void* const* d_in, const int* in_sizes, int n_in,
                              void* d_out, int out_size)
{
    (void)in_sizes; (void)n_in; (void)out_size;
    const float* img  = (const float*)d_in[0];
    const float* wimg = (const float*)d_in[1];
    const float* wc   = (const float*)d_in[2];
    const float* gg   = (const float*)d_in[3];
    const float* bb   = (const float*)d_in[4];
    const float* mm   = (const float*)d_in[5];
    const float* vv   = (const float*)d_in[6];
    float* out = (float*)d_out;

    static int attr_set = 0;
    if (!attr_set) {
        cudaFuncSetAttribute(attn_kernel,
                             cudaFuncAttributeMaxDynamicSharedMemorySize, SMEM4_BYTES);
        cudaFuncSetAttribute(qkv_kernel,
                             cudaFuncAttributeMaxDynamicSharedMemorySize, QKV_SMEM);
        attr_set = 1;
    }

    prep_kernel<<<81, 256>>>(wc, gg, bb, mm, vv);
    zero_border_kernel<<<(BN_*2560 + BN_*H_*8 + 255)/256, 256>>>();

    dim3 qgrid(HW_/128, BN_);   // 175 x 6
    qkv_kernel<<<qgrid, 128, QKV_SMEM>>>(img, wimg);

    dim3 agrid((W_ + 15)/16, H_/8, BN_);   // 13 x 14 x 6
    attn_kernel<<<agrid, 256, SMEM4_BYTES>>>(out);
}

// round 10
// speedup vs baseline: 1.2267x; 1.2267x over previous
#include <cuda_runtime.h>
#include <math.h>

// Problem constants
#define H_    112
#define W_    200
#define HW_   (H_*W_)        // 22400
#define C_    64
#define BN_   6
#define PAD_  4
#define HP_   (H_ + 2*PAD_)  // 120
#define WP_   (W_ + 2*PAD_)  // 208
#define HPWP_ (HP_*WP_)      // 24960
#define QW_   208
#define NTAP  81

// tf32 round (rna), b32 destination
__device__ __forceinline__ float tf32r(float x) {
    unsigned u;
    asm("cvt.rna.tf32.f32 %0, %1;" : "=r"(u) : "f"(x));
    return __uint_as_float(u);
}

__device__ __forceinline__ void mma_tf32(float c[4], const float a[4], float b0, float b1) {
    const unsigned* A = (const unsigned*)a;
    asm("mma.sync.aligned.m16n8k8.row.col.f32.tf32.tf32.f32 "
        "{%0,%1,%2,%3}, {%4,%5,%6,%7}, {%8,%9}, {%0,%1,%2,%3};"
        : "+f"(c[0]), "+f"(c[1]), "+f"(c[2]), "+f"(c[3])
        : "r"(A[0]), "r"(A[1]), "r"(A[2]), "r"(A[3]),
          "r"(__float_as_uint(b0)), "r"(__float_as_uint(b1)));
}

// ---------------- scratch -----------------------------------------------------
__device__ float4 g_q   [BN_*H_*QW_*16];  // [n][h][w208][c] channel-last tf32
__device__ float4 g_kpad[BN_*HPWP_*16];   // [n][hp][wp][c] padded channel-last
__device__ float4 g_vpad[BN_*HPWP_*16];
__device__ float4 g_Wf4 [5*8*4*32];       // weight A-fragments: [l][k0][m0][lane]{4}
__device__ float  g_bf  [5*64];           // folded bias

// ---------------- prep: BN fold + weight fragment packing --------------------
__global__ void prep_kernel(const float* __restrict__ wc, const float* __restrict__ gam,
                            const float* __restrict__ bet, const float* __restrict__ mu,
                            const float* __restrict__ var) {
    int idx = blockIdx.x * 256 + threadIdx.x;
    if (idx < 5*8*4*32*4) {
        int l  = idx >> 12;
        int r  = idx & 4095;
        int k0 = r >> 9;
        int r2 = r & 511;
        int m0 = r2 >> 7;
        int r3 = r2 & 127;
        int lane = r3 >> 2;
        int j    = r3 & 3;
        int g  = lane >> 2;
        int tg = lane & 3;
        int o  = m0*16 + g + ((j & 1) ? 8 : 0);
        int ci = k0*8 + tg + ((j >= 2) ? 4 : 0);
        float s = gam[l*64 + o] * rsqrtf(var[l*64 + o] + 1e-5f);
        ((float*)g_Wf4)[idx] = tf32r(s * wc[(l*64 + o)*64 + ci]);
    }
    if (idx < 5*64) {
        float s = gam[idx] * rsqrtf(var[idx] + 1e-5f);
        g_bf[idx] = bet[idx] - s * mu[idx];
    }
}

// ---------------- zero pad borders of K/V and Q column pad -------------------
__global__ void zero_border_kernel() {
    int idx = blockIdx.x * 256 + threadIdx.x;
    const int kvTotal = BN_ * 2560;
    float4 z = make_float4(0.f, 0.f, 0.f, 0.f);
    if (idx < kvTotal) {
        int n = idx / 2560;
        int j = idx - n * 2560;
        int row, col;
        if (j < 1664) {
            int r = j / 208;
            col = j - r * 208;
            row = (r < 4) ? r : (112 + r);
        } else {
            int k = j - 1664;
            row = 4 + (k >> 3);
            int c = k & 7;
            col = (c < 4) ? c : (200 + c);
        }
        size_t base = ((size_t)(n * HP_ + row) * WP_ + col) * 16;
        #pragma unroll
        for (int c4 = 0; c4 < 16; c4++) {
            g_kpad[base + c4] = z;
            g_vpad[base + c4] = z;
        }
    } else if (idx < kvTotal + BN_*H_*8) {
        int qi = idx - kvTotal;
        int n = qi / (H_*8);
        int rr = qi - n*(H_*8);
        int h = rr >> 3;
        int c = rr & 7;
        size_t base = ((size_t)(n*H_ + h)*QW_ + 200 + c) * 16;
        #pragma unroll
        for (int c4 = 0; c4 < 16; c4++) g_q[base + c4] = z;
    }
}

// ---------------- fused 5-layer QKV via tensor cores (proven round-8) --------
#define XSTRIDE 40
#define BUF_F   (64*XSTRIDE)
#define QKV_SMEM (4*2*BUF_F*4)

__device__ __forceinline__ void stage_tile(const float* __restrict__ src, float* buf, int lane) {
    int ci0 = lane >> 3;
    int px4 = lane & 7;
    #pragma unroll
    for (int it = 0; it < 16; it++) {
        int ci = it*4 + ci0;
        float4 v = *(const float4*)(src + (size_t)ci*HW_ + px4*4);
        v.x = tf32r(v.x); v.y = tf32r(v.y); v.z = tf32r(v.z); v.w = tf32r(v.w);
        *(float4*)(buf + ci*XSTRIDE + px4*4) = v;
    }
}

__device__ __forceinline__ void layer_mma(const float* buf, int l, int lane, float c[4][4][4]) {
    int g = lane >> 2, tg = lane & 3;
    #pragma unroll
    for (int m = 0; m < 4; m++)
        #pragma unroll
        for (int nt = 0; nt < 4; nt++)
            #pragma unroll
            for (int j = 0; j < 4; j++) c[m][nt][j] = 0.f;

    const float4* wf = g_Wf4 + (size_t)l*8*4*32;
    #pragma unroll
    for (int k0 = 0; k0 < 8; k0++) {
        float4 a[4];
        #pragma unroll
        for (int m = 0; m < 4; m++)
            a[m] = __ldg(wf + (k0*4 + m)*32 + lane);
        #pragma unroll
        for (int nt = 0; nt < 4; nt++) {
            float b0 = buf[(k0*8 + tg)    *XSTRIDE + nt*8 + g];
            float b1 = buf[(k0*8 + tg + 4)*XSTRIDE + nt*8 + g];
            #pragma unroll
            for (int m = 0; m < 4; m++)
                mma_tf32(c[m][nt], (const float*)&a[m], b0, b1);
        }
    }
}

__device__ __forceinline__ void epi_smem(float c[4][4][4], float* bufo, int l, int lane) {
    int g = lane >> 2, tg = lane & 3;
    #pragma unroll
    for (int m = 0; m < 4; m++) {
        float b0 = g_bf[l*64 + m*16 + g];
        float b1 = g_bf[l*64 + m*16 + g + 8];
        #pragma unroll
        for (int nt = 0; nt < 4; nt++) {
            int px = nt*8 + 2*tg;
            bufo[(m*16 + g)    *XSTRIDE + px]     = tf32r(fmaxf(c[m][nt][0] + b0, 0.f));
            bufo[(m*16 + g)    *XSTRIDE + px + 1] = tf32r(fmaxf(c[m][nt][1] + b0, 0.f));
            bufo[(m*16 + g + 8)*XSTRIDE + px]     = tf32r(fmaxf(c[m][nt][2] + b1, 0.f));
            bufo[(m*16 + g + 8)*XSTRIDE + px + 1] = tf32r(fmaxf(c[m][nt][3] + b1, 0.f));
        }
    }
}

__device__ __forceinline__ void epi_gmem(float c[4][4][4], float* base, int l, int lane, int px0) {
    int g = lane >> 2, tg = lane & 3;
    float bs0[4], bs1[4];
    #pragma unroll
    for (int m = 0; m < 4; m++) {
        bs0[m] = g_bf[l*64 + m*16 + g];
        bs1[m] = g_bf[l*64 + m*16 + g + 8];
    }
    #pragma unroll
    for (int nt = 0; nt < 4; nt++) {
        #pragma unroll
        for (int j = 0; j < 2; j++) {
            int px = px0 + nt*8 + 2*tg + j;
            int h = px / W_;
            int w = px - h*W_;
            float* p = base + ((size_t)h*WP_ + w)*64;
            #pragma unroll
            for (int m = 0; m < 4; m++) {
                p[m*16 + g]     = tf32r(fmaxf(c[m][nt][j]     + bs0[m], 0.f));
                p[m*16 + g + 8] = tf32r(fmaxf(c[m][nt][2 + j] + bs1[m], 0.f));
            }
        }
    }
}

__global__ __launch_bounds__(128) void qkv_kernel(const float* __restrict__ img,
                                                  const float* __restrict__ wimg)
{
    extern __shared__ float xs[];
    const int tid = threadIdx.x;
    const int wid = tid >> 5;
    const int lane = tid & 31;
    const int n = blockIdx.y;
    const int px0 = (blockIdx.x*4 + wid) * 32;

    float* bufA = xs + wid * (2*BUF_F);
    float* bufB = bufA + BUF_F;
    float c[4][4][4];

    const float* wsrc = wimg + (size_t)n*C_*HW_ + px0;
    const float* isrc = img  + (size_t)n*C_*HW_ + px0;
    float* qb = (float*)g_q    + (size_t)n*H_*QW_*64;
    float* kb = (float*)g_kpad + (((size_t)n*HP_ + PAD_)*WP_ + PAD_)*64;
    float* vb = (float*)g_vpad + (((size_t)n*HP_ + PAD_)*WP_ + PAD_)*64;

    stage_tile(wsrc, bufA, lane);  __syncwarp();
    layer_mma(bufA, 4, lane, c);   epi_gmem(c, vb, 4, lane, px0);
    layer_mma(bufA, 2, lane, c);   epi_smem(c, bufB, 2, lane);  __syncwarp();
    layer_mma(bufB, 3, lane, c);   epi_gmem(c, kb, 3, lane, px0);
    stage_tile(isrc, bufA, lane);  __syncwarp();
    layer_mma(bufA, 0, lane, c);   epi_smem(c, bufB, 0, lane);  __syncwarp();
    layer_mma(bufB, 1, lane, c);   epi_gmem(c, qb, 1, lane, px0);
}

// ---------------- attention: 2x32ch passes + direct band store ---------------
#define TR_   16
#define TC_   24
#define CPAD2 36                        // 32 ch + 4 pad (conflict-free B loads)
#define KV2_F  (TR_*TC_*CPAD2)          // 13824 f
#define SACC_F (8*16*84)                // 10752 f
#define SMEM2_F (KV2_F + SACC_F + 8*16)
#define SMEM2_BYTES (SMEM2_F*4)         // 98816 B -> 2 CTAs/SM

__device__ __forceinline__ void band_store(float* sa, float v, int px, int col,
                                           int di, int acc) {
    int dj = col - px;
    if ((unsigned)dj <= 8u) {
        float* p = sa + px*84 + di*9 + dj;
        if (acc) *p += v; else *p = v;
    }
}

__global__ __launch_bounds__(256, 2) void attn_kernel(float* __restrict__ out)
{
    extern __shared__ float smem[];
    float* kv   = smem;                 // [16][24][36]
    float* sacc = smem + KV2_F;         // [8][16][84]
    float* sinv = sacc + SACC_F;        // [8][16]

    const int tid  = threadIdx.x;
    const int wid  = tid >> 5;
    const int lane = tid & 31;
    const int g    = lane >> 2;
    const int tg   = lane & 3;
    const int n  = blockIdx.z;
    const int h0 = blockIdx.y * 8;
    const int w0 = blockIdx.x * 16;
    const int h  = h0 + wid;

    // ---- Q fragments for all 64 channels ----
    float qa[8][4];
    {
        const float* qb = (const float*)g_q + ((size_t)(n*H_ + h)*QW_) * 64;
        #pragma unroll
        for (int k = 0; k < 8; k++) {
            qa[k][0] = qb[(w0 + g)    *64 + k*8 + tg];
            qa[k][1] = qb[(w0 + g + 8)*64 + k*8 + tg];
            qa[k][2] = qb[(w0 + g)    *64 + k*8 + tg + 4];
            qa[k][3] = qb[(w0 + g + 8)*64 + k*8 + tg + 4];
        }
    }

    float* sa = sacc + wid*(16*84);

    // ---- phase 1: similarity, two 32-channel passes, direct band store ----
    #pragma unroll 1
    for (int cp = 0; cp < 2; cp++) {
        __syncthreads();
        {
            const float4* kb = g_kpad + (size_t)(n*HP_ + h0) * WP_ * 16;
            for (int i = tid; i < TR_*TC_*8; i += 256) {
                int px = i >> 3, c4 = i & 7;
                int r = px / TC_, c = px - r*TC_;
                int pcol = w0 + c; if (pcol > 207) pcol = 207;
                float4 v = kb[((size_t)r*WP_ + pcol)*16 + cp*8 + c4];
                *(float4*)(kv + px*CPAD2 + c4*4) = v;
            }
        }
        __syncthreads();
        #pragma unroll 1
        for (int di = 0; di < 9; di++) {
            float c0[3][4];
            #pragma unroll
            for (int nt = 0; nt < 3; nt++)
                #pragma unroll
                for (int j = 0; j < 4; j++) c0[nt][j] = 0.f;
            const float* krow = kv + (wid + di)*(TC_*CPAD2);
            #pragma unroll
            for (int nt = 0; nt < 3; nt++) {
                const float* kc = krow + (nt*8 + g)*CPAD2;
                #pragma unroll
                for (int k = 0; k < 4; k++) {
                    float b0 = kc[k*8 + tg];
                    float b1 = kc[k*8 + tg + 4];
                    mma_tf32(c0[nt], qa[cp*4 + k], b0, b1);
                }
            }
            #pragma unroll
            for (int nt = 0; nt < 3; nt++) {
                int colb = nt*8 + 2*tg;
                band_store(sa, c0[nt][0], g,     colb,     di, cp);
                band_store(sa, c0[nt][1], g,     colb + 1, di, cp);
                band_store(sa, c0[nt][2], g + 8, colb,     di, cp);
                band_store(sa, c0[nt][3], g + 8, colb + 1, di, cp);
            }
        }
    }
    __syncwarp();

    // ---- softmax (2 lanes per px) ----
    {
        int px   = lane & 15;
        int half = lane >> 4;
        float* sp = sa + px*84;
        int t0 = half * 41;
        int tc = 41 - half;
        float mx = -1e30f;
        for (int t = 0; t < tc; t++) {
            float v = sp[t0 + t] * 0.125f;
            mx = fmaxf(mx, v);
        }
        mx = fmaxf(mx, __shfl_xor_sync(0xffffffffu, mx, 16));
        float sum = 0.f;
        for (int t = 0; t < tc; t++) {
            float e = __expf(sp[t0 + t] * 0.125f - mx);
            sum += e;
            sp[t0 + t] = tf32r(e);
        }
        sum += __shfl_xor_sync(0xffffffffu, sum, 16);
        if (half == 0) sinv[wid*16 + px] = 1.f / sum;
    }

    // ---- phase 2: weighting, two 32-channel passes ----
    #pragma unroll 1
    for (int vp = 0; vp < 2; vp++) {
        __syncthreads();
        {
            const float4* vb = g_vpad + (size_t)(n*HP_ + h0) * WP_ * 16;
            for (int i = tid; i < TR_*TC_*8; i += 256) {
                int px = i >> 3, c4 = i & 7;
                int r = px / TC_, c = px - r*TC_;
                int pcol = w0 + c; if (pcol > 207) pcol = 207;
                float4 v = vb[((size_t)r*WP_ + pcol)*16 + vp*8 + c4];
                *(float4*)(kv + px*CPAD2 + c4*4) = v;
            }
        }
        __syncthreads();

        float oc[2][2][4];
        #pragma unroll
        for (int mt = 0; mt < 2; mt++)
            #pragma unroll
            for (int nt = 0; nt < 2; nt++)
                #pragma unroll
                for (int j = 0; j < 4; j++) oc[mt][nt][j] = 0.f;

        #pragma unroll 1
        for (int di = 0; di < 9; di++) {
            const float* vrow = kv + (wid + di)*(TC_*CPAD2);
            #pragma unroll
            for (int kst = 0; kst < 3; kst++) {
                float bb[2][2];
                #pragma unroll
                for (int nt = 0; nt < 2; nt++) {
                    int i0 = nt*8 + g;
                    int j0 = kst*8 + tg;
                    int dj0 = j0 - i0;
                    int dj1 = dj0 + 4;
                    bb[nt][0] = ((unsigned)dj0 <= 8u) ? sa[i0*84 + di*9 + dj0] : 0.f;
                    bb[nt][1] = ((unsigned)dj1 <= 8u) ? sa[i0*84 + di*9 + dj1] : 0.f;
                }
                #pragma unroll
                for (int mt = 0; mt < 2; mt++) {
                    float av[4];
                    av[0] = vrow[(kst*8 + tg)    *CPAD2 + mt*16 + g];
                    av[1] = vrow[(kst*8 + tg)    *CPAD2 + mt*16 + g + 8];
                    av[2] = vrow[(kst*8 + tg + 4)*CPAD2 + mt*16 + g];
                    av[3] = vrow[(kst*8 + tg + 4)*CPAD2 + mt*16 + g + 8];
                    mma_tf32(oc[mt][0], av, bb[0][0], bb[0][1]);
                    mma_tf32(oc[mt][1], av, bb[1][0], bb[1][1]);
                }
            }
        }

        // store this pass's 32 channels
        #pragma unroll
        for (int nt = 0; nt < 2; nt++) {
            int pxl = nt*8 + 2*tg;
            float is0 = sinv[wid*16 + pxl];
            float is1 = sinv[wid*16 + pxl + 1];
            int w = w0 + pxl;
            #pragma unroll
            for (int mt = 0; mt < 2; mt++) {
                int c  = vp*32 + mt*16 + g;
                float* ob0 = out + ((size_t)(n*C_ + c)*H_ + h)*W_;
                float* ob1 = out + ((size_t)(n*C_ + c + 8)*H_ + h)*W_;
                if (w < W_) {
                    ob0[w] = oc[mt][nt][0] * is0;
                    ob1[w] = oc[mt][nt][2] * is0;
                }
                if (w + 1 < W_) {
                    ob0[w+1] = oc[mt][nt][1] * is1;
                    ob1[w+1] = oc[mt][nt][3] * is1;
                }
            }
        }
    }
}

// ---------------- launch ------------------------------------------------------
extern "C" void kernel_launch(void* const* d_in, const int* in_sizes, int n_in,
                              void* d_out, int out_size)
{
    (void)in_sizes; (void)n_in; (void)out_size;
    const float* img  = (const float*)d_in[0];
    const float* wimg = (const float*)d_in[1];
    const float* wc   = (const float*)d_in[2];
    const float* gg   = (const float*)d_in[3];
    const float* bb   = (const float*)d_in[4];
    const float* mm   = (const float*)d_in[5];
    const float* vv   = (const float*)d_in[6];
    float* out = (float*)d_out;

    static int attr_set = 0;
    if (!attr_set) {
        cudaFuncSetAttribute(attn_kernel,
                             cudaFuncAttributeMaxDynamicSharedMemorySize, SMEM2_BYTES);
        cudaFuncSetAttribute(qkv_kernel,
                             cudaFuncAttributeMaxDynamicSharedMemorySize, QKV_SMEM);
        attr_set = 1;
    }

    prep_kernel<<<81, 256>>>(wc, gg, bb, mm, vv);
    zero_border_kernel<<<(BN_*2560 + BN_*H_*8 + 255)/256, 256>>>();

    dim3 qgrid(HW_/128, BN_);   // 175 x 6
    qkv_kernel<<<qgrid, 128, QKV_SMEM>>>(img, wimg);

    dim3 agrid((W_ + 15)/16, H_/8, BN_);   // 13 x 14 x 6
    attn_kernel<<<agrid, 256, SMEM2_BYTES>>>(out);
}

// round 11
// speedup vs baseline: 1.3468x; 1.0978x over previous
#include <cuda_runtime.h>
#include <cuda_fp16.h>
#include <math.h>

// Problem constants
#define H_    112
#define W_    200
#define HW_   (H_*W_)        // 22400
#define C_    64
#define BN_   6
#define PAD_  4
#define HP_   (H_ + 2*PAD_)  // 120
#define WP_   (W_ + 2*PAD_)  // 208
#define HPWP_ (HP_*WP_)      // 24960
#define QW_   208
#define NTAP  81

// tf32 round (rna), b32 destination
__device__ __forceinline__ float tf32r(float x) {
    unsigned u;
    asm("cvt.rna.tf32.f32 %0, %1;" : "=r"(u) : "f"(x));
    return __uint_as_float(u);
}

__device__ __forceinline__ void mma_tf32(float c[4], const float a[4], float b0, float b1) {
    const unsigned* A = (const unsigned*)a;
    asm("mma.sync.aligned.m16n8k8.row.col.f32.tf32.tf32.f32 "
        "{%0,%1,%2,%3}, {%4,%5,%6,%7}, {%8,%9}, {%0,%1,%2,%3};"
        : "+f"(c[0]), "+f"(c[1]), "+f"(c[2]), "+f"(c[3])
        : "r"(A[0]), "r"(A[1]), "r"(A[2]), "r"(A[3]),
          "r"(__float_as_uint(b0)), "r"(__float_as_uint(b1)));
}

// fp16 mma, fp32 accumulate: D[16px x 8col] += A[16px x 16ch] * B[16ch x 8col]
__device__ __forceinline__ void mma_f16(float c[4], const unsigned a[4],
                                        unsigned b0, unsigned b1) {
    asm("mma.sync.aligned.m16n8k16.row.col.f32.f16.f16.f32 "
        "{%0,%1,%2,%3}, {%4,%5,%6,%7}, {%8,%9}, {%0,%1,%2,%3};"
        : "+f"(c[0]), "+f"(c[1]), "+f"(c[2]), "+f"(c[3])
        : "r"(a[0]), "r"(a[1]), "r"(a[2]), "r"(a[3]), "r"(b0), "r"(b1));
}

// ---------------- scratch -----------------------------------------------------
__device__ unsigned g_qh  [BN_*H_*QW_*32];   // Q fp16, [n][h][w208][ch] (u32 = 2ch)
__device__ unsigned g_kph [BN_*HPWP_*32];    // K fp16, padded channel-last
__device__ float4   g_vpad[BN_*HPWP_*16];    // V fp32, padded channel-last (tf32 vals)
__device__ float4   g_Wf4 [5*8*4*32];        // conv weight A-frags: [l][k0][m0][lane]{4}
__device__ float    g_bf  [5*64];            // folded bias

// ---------------- prep: BN fold + weight frags + border zero (one launch) ----
// grid 81 x 256 = 20736 threads: weight frags use idx<20480; border uses all 20736.
__global__ void prep_kernel(const float* __restrict__ wc, const float* __restrict__ gam,
                            const float* __restrict__ bet, const float* __restrict__ mu,
                            const float* __restrict__ var) {
    int idx = blockIdx.x * 256 + threadIdx.x;
    if (idx < 5*8*4*32*4) {
        int l  = idx >> 12;
        int r  = idx & 4095;
        int k0 = r >> 9;
        int r2 = r & 511;
        int m0 = r2 >> 7;
        int r3 = r2 & 127;
        int lane = r3 >> 2;
        int j    = r3 & 3;
        int g  = lane >> 2;
        int tg = lane & 3;
        int o  = m0*16 + g + ((j & 1) ? 8 : 0);
        int ci = k0*8 + tg + ((j >= 2) ? 4 : 0);
        float s = gam[l*64 + o] * rsqrtf(var[l*64 + o] + 1e-5f);
        ((float*)g_Wf4)[idx] = tf32r(s * wc[(l*64 + o)*64 + ci]);
    }
    if (idx < 5*64) {
        float s = gam[idx] * rsqrtf(var[idx] + 1e-5f);
        g_bf[idx] = bet[idx] - s * mu[idx];
    }
    // border zeroing: idx in [0, 20736) = KV border (15360) + Q col pad (5376)
    const int kvTotal = BN_ * 2560;
    uint4 zu = make_uint4(0, 0, 0, 0);
    float4 zf = make_float4(0.f, 0.f, 0.f, 0.f);
    if (idx < kvTotal) {
        int n = idx / 2560;
        int j = idx - n * 2560;
        int row, col;
        if (j < 1664) {
            int r = j / 208;
            col = j - r * 208;
            row = (r < 4) ? r : (112 + r);
        } else {
            int k = j - 1664;
            row = 4 + (k >> 3);
            int c = k & 7;
            col = (c < 4) ? c : (200 + c);
        }
        size_t px = (size_t)(n * HP_ + row) * WP_ + col;
        uint4* kp = (uint4*)(g_kph + px*32);
        #pragma unroll
        for (int c8 = 0; c8 < 8; c8++) kp[c8] = zu;
        #pragma unroll
        for (int c4 = 0; c4 < 16; c4++) g_vpad[px*16 + c4] = zf;
    } else if (idx < kvTotal + BN_*H_*8) {
        int qi = idx - kvTotal;
        int n = qi / (H_*8);
        int rr = qi - n*(H_*8);
        int h = rr >> 3;
        int c = rr & 7;
        size_t px = (size_t)(n*H_ + h)*QW_ + 200 + c;
        uint4* qp = (uint4*)(g_qh + px*32);
        #pragma unroll
        for (int c8 = 0; c8 < 8; c8++) qp[c8] = zu;
    }
}

// ---------------- fused 5-layer QKV via tensor cores (round-8 core) ----------
#define XSTRIDE 40
#define BUF_F   (64*XSTRIDE)
#define QKV_SMEM (4*2*BUF_F*4)

__device__ __forceinline__ void stage_tile(const float* __restrict__ src, float* buf, int lane) {
    int ci0 = lane >> 3;
    int px4 = lane & 7;
    #pragma unroll
    for (int it = 0; it < 16; it++) {
        int ci = it*4 + ci0;
        float4 v = *(const float4*)(src + (size_t)ci*HW_ + px4*4);
        v.x = tf32r(v.x); v.y = tf32r(v.y); v.z = tf32r(v.z); v.w = tf32r(v.w);
        *(float4*)(buf + ci*XSTRIDE + px4*4) = v;
    }
}

__device__ __forceinline__ void layer_mma(const float* buf, int l, int lane, float c[4][4][4]) {
    int g = lane >> 2, tg = lane & 3;
    #pragma unroll
    for (int m = 0; m < 4; m++)
        #pragma unroll
        for (int nt = 0; nt < 4; nt++)
            #pragma unroll
            for (int j = 0; j < 4; j++) c[m][nt][j] = 0.f;

    const float4* wf = g_Wf4 + (size_t)l*8*4*32;
    #pragma unroll
    for (int k0 = 0; k0 < 8; k0++) {
        float4 a[4];
        #pragma unroll
        for (int m = 0; m < 4; m++)
            a[m] = __ldg(wf + (k0*4 + m)*32 + lane);
        #pragma unroll
        for (int nt = 0; nt < 4; nt++) {
            float b0 = buf[(k0*8 + tg)    *XSTRIDE + nt*8 + g];
            float b1 = buf[(k0*8 + tg + 4)*XSTRIDE + nt*8 + g];
            #pragma unroll
            for (int m = 0; m < 4; m++)
                mma_tf32(c[m][nt], (const float*)&a[m], b0, b1);
        }
    }
}

__device__ __forceinline__ void epi_smem(float c[4][4][4], float* bufo, int l, int lane) {
    int g = lane >> 2, tg = lane & 3;
    #pragma unroll
    for (int m = 0; m < 4; m++) {
        float b0 = g_bf[l*64 + m*16 + g];
        float b1 = g_bf[l*64 + m*16 + g + 8];
        #pragma unroll
        for (int nt = 0; nt < 4; nt++) {
            int px = nt*8 + 2*tg;
            bufo[(m*16 + g)    *XSTRIDE + px]     = tf32r(fmaxf(c[m][nt][0] + b0, 0.f));
            bufo[(m*16 + g)    *XSTRIDE + px + 1] = tf32r(fmaxf(c[m][nt][1] + b0, 0.f));
            bufo[(m*16 + g + 8)*XSTRIDE + px]     = tf32r(fmaxf(c[m][nt][2] + b1, 0.f));
            bufo[(m*16 + g + 8)*XSTRIDE + px + 1] = tf32r(fmaxf(c[m][nt][3] + b1, 0.f));
        }
    }
}

// fp32 (tf32-rounded) channel-last gmem epilogue — used for V
__device__ __forceinline__ void epi_gmem(float c[4][4][4], float* base, int l, int lane, int px0) {
    int g = lane >> 2, tg = lane & 3;
    float bs0[4], bs1[4];
    #pragma unroll
    for (int m = 0; m < 4; m++) {
        bs0[m] = g_bf[l*64 + m*16 + g];
        bs1[m] = g_bf[l*64 + m*16 + g + 8];
    }
    #pragma unroll
    for (int nt = 0; nt < 4; nt++) {
        #pragma unroll
        for (int j = 0; j < 2; j++) {
            int px = px0 + nt*8 + 2*tg + j;
            int h = px / W_;
            int w = px - h*W_;
            float* p = base + ((size_t)h*WP_ + w)*64;
            #pragma unroll
            for (int m = 0; m < 4; m++) {
                p[m*16 + g]     = tf32r(fmaxf(c[m][nt][j]     + bs0[m], 0.f));
                p[m*16 + g + 8] = tf32r(fmaxf(c[m][nt][2 + j] + bs1[m], 0.f));
            }
        }
    }
}

// fp16 channel-last gmem epilogue — used for Q and K
__device__ __forceinline__ void epi_gmem_h(float c[4][4][4], __half* base, int l, int lane, int px0) {
    int g = lane >> 2, tg = lane & 3;
    float bs0[4], bs1[4];
    #pragma unroll
    for (int m = 0; m < 4; m++) {
        bs0[m] = g_bf[l*64 + m*16 + g];
        bs1[m] = g_bf[l*64 + m*16 + g + 8];
    }
    #pragma unroll
    for (int nt = 0; nt < 4; nt++) {
        #pragma unroll
        for (int j = 0; j < 2; j++) {
            int px = px0 + nt*8 + 2*tg + j;
            int h = px / W_;
            int w = px - h*W_;
            __half* p = base + ((size_t)h*WP_ + w)*64;
            #pragma unroll
            for (int m = 0; m < 4; m++) {
                p[m*16 + g]     = __float2half_rn(fmaxf(c[m][nt][j]     + bs0[m], 0.f));
                p[m*16 + g + 8] = __float2half_rn(fmaxf(c[m][nt][2 + j] + bs1[m], 0.f));
            }
        }
    }
}

__global__ __launch_bounds__(128) void qkv_kernel(const float* __restrict__ img,
                                                  const float* __restrict__ wimg)
{
    extern __shared__ float xs[];
    const int tid = threadIdx.x;
    const int wid = tid >> 5;
    const int lane = tid & 31;
    const int n = blockIdx.y;
    const int px0 = (blockIdx.x*4 + wid) * 32;

    float* bufA = xs + wid * (2*BUF_F);
    float* bufB = bufA + BUF_F;
    float c[4][4][4];

    const float* wsrc = wimg + (size_t)n*C_*HW_ + px0;
    const float* isrc = img  + (size_t)n*C_*HW_ + px0;
    __half* qb = (__half*)g_qh  + (size_t)n*H_*QW_*64;   // stride WP_==QW_
    __half* kb = (__half*)g_kph + (((size_t)n*HP_ + PAD_)*WP_ + PAD_)*64;
    float*  vb = (float*)g_vpad + (((size_t)n*HP_ + PAD_)*WP_ + PAD_)*64;

    stage_tile(wsrc, bufA, lane);  __syncwarp();
    layer_mma(bufA, 4, lane, c);   epi_gmem(c, vb, 4, lane, px0);
    layer_mma(bufA, 2, lane, c);   epi_smem(c, bufB, 2, lane);  __syncwarp();
    layer_mma(bufB, 3, lane, c);   epi_gmem_h(c, kb, 3, lane, px0);
    stage_tile(isrc, bufA, lane);  __syncwarp();
    layer_mma(bufA, 0, lane, c);   epi_smem(c, bufB, 0, lane);  __syncwarp();
    layer_mma(bufB, 1, lane, c);   epi_gmem_h(c, qb, 1, lane, px0);
}

// ---------------- attention: fp16 phase-1, tf32 phase-2 ----------------------
#define TR_   16
#define TC_   24
#define CPAD2 36                        // fp32 V tile: 32 ch + 4 pad
#define CPADH 20                        // fp16 K tile: 16 u32 (32ch) + 4 pad
#define KV2_F  (TR_*TC_*CPAD2)          // 13824 f (union buffer; K needs 7680 u32)
#define SACC_F (8*16*84)                // 10752 f
#define SMEM2_F (KV2_F + SACC_F + 8*16)
#define SMEM2_BYTES (SMEM2_F*4)         // 98816 B -> 2 CTAs/SM

__device__ __forceinline__ void band_store(float* sa, float v, int px, int col,
                                           int di, int acc) {
    int dj = col - px;
    if ((unsigned)dj <= 8u) {
        float* p = sa + px*84 + di*9 + dj;
        if (acc) *p += v; else *p = v;
    }
}

__global__ __launch_bounds__(256, 2) void attn_kernel(float* __restrict__ out)
{
    extern __shared__ float smem[];
    float*    kv  = smem;               // union: K fp16 [16][24][20 u32] / V fp32 [16][24][36]
    unsigned* kvu = (unsigned*)smem;
    float* sacc = smem + KV2_F;         // [8][16][84]
    float* sinv = sacc + SACC_F;        // [8][16]

    const int tid  = threadIdx.x;
    const int wid  = tid >> 5;
    const int lane = tid & 31;
    const int g    = lane >> 2;
    const int tg   = lane & 3;
    const int n  = blockIdx.z;
    const int h0 = blockIdx.y * 8;
    const int w0 = blockIdx.x * 16;
    const int h  = h0 + wid;

    // ---- Q fp16 A-fragments: 4 k-steps of 16 ch ----
    unsigned qa[4][4];
    {
        const unsigned* q0 = g_qh + ((size_t)(n*H_ + h)*QW_ + (w0 + g))     * 32;
        const unsigned* q1 = g_qh + ((size_t)(n*H_ + h)*QW_ + (w0 + g + 8)) * 32;
        #pragma unroll
        for (int ks = 0; ks < 4; ks++) {
            qa[ks][0] = q0[ks*8 + tg];
            qa[ks][1] = q1[ks*8 + tg];
            qa[ks][2] = q0[ks*8 + tg + 4];
            qa[ks][3] = q1[ks*8 + tg + 4];
        }
    }

    float* sa = sacc + wid*(16*84);

    // ---- phase 1: similarity, fp16 mma, two 32-ch passes, direct band store ----
    #pragma unroll 1
    for (int cp = 0; cp < 2; cp++) {
        __syncthreads();
        {
            const uint4* kb = (const uint4*)(g_kph + (size_t)(n*HP_ + h0) * WP_ * 32);
            for (int i = tid; i < TR_*TC_*4; i += 256) {
                int px = i >> 2, c4 = i & 3;
                int r = px / TC_, c = px - r*TC_;
                int pcol = w0 + c; if (pcol > 207) pcol = 207;
                uint4 v = kb[((size_t)r*WP_ + pcol)*8 + cp*4 + c4];
                *(uint4*)(kvu + px*CPADH + c4*4) = v;
            }
        }
        __syncthreads();
        #pragma unroll 1
        for (int di = 0; di < 9; di++) {
            float c0[3][4];
            #pragma unroll
            for (int nt = 0; nt < 3; nt++)
                #pragma unroll
                for (int j = 0; j < 4; j++) c0[nt][j] = 0.f;
            const unsigned* krow = kvu + (wid + di)*(TC_*CPADH);
            #pragma unroll
            for (int nt = 0; nt < 3; nt++) {
                const unsigned* kc = krow + (nt*8 + g)*CPADH;
                #pragma unroll
                for (int ks = 0; ks < 2; ks++) {
                    unsigned b0 = kc[ks*8 + tg];
                    unsigned b1 = kc[ks*8 + tg + 4];
                    mma_f16(c0[nt], qa[cp*2 + ks], b0, b1);
                }
            }
            #pragma unroll
            for (int nt = 0; nt < 3; nt++) {
                int colb = nt*8 + 2*tg;
                band_store(sa, c0[nt][0], g,     colb,     di, cp);
                band_store(sa, c0[nt][1], g,     colb + 1, di, cp);
                band_store(sa, c0[nt][2], g + 8, colb,     di, cp);
                band_store(sa, c0[nt][3], g + 8, colb + 1, di, cp);
            }
        }
    }
    __syncwarp();

    // ---- softmax (2 lanes per px) ----
    {
        int px   = lane & 15;
        int half = lane >> 4;
        float* sp = sa + px*84;
        int t0 = half * 41;
        int tc = 41 - half;
        float mx = -1e30f;
        for (int t = 0; t < tc; t++) {
            float v = sp[t0 + t] * 0.125f;
            mx = fmaxf(mx, v);
        }
        mx = fmaxf(mx, __shfl_xor_sync(0xffffffffu, mx, 16));
        float sum = 0.f;
        for (int t = 0; t < tc; t++) {
            float e = __expf(sp[t0 + t] * 0.125f - mx);
            sum += e;
            sp[t0 + t] = tf32r(e);
        }
        sum += __shfl_xor_sync(0xffffffffu, sum, 16);
        if (half == 0) sinv[wid*16 + px] = 1.f / sum;
    }

    // ---- phase 2: weighting, tf32, two 32-channel passes (proven R10) ----
    #pragma unroll 1
    for (int vp = 0; vp < 2; vp++) {
        __syncthreads();
        {
            const float4* vb = g_vpad + (size_t)(n*HP_ + h0) * WP_ * 16;
            for (int i = tid; i < TR_*TC_*8; i += 256) {
                int px = i >> 3, c4 = i & 7;
                int r = px / TC_, c = px - r*TC_;
                int pcol = w0 + c; if (pcol > 207) pcol = 207;
                float4 v = vb[((size_t)r*WP_ + pcol)*16 + vp*8 + c4];
                *(float4*)(kv + px*CPAD2 + c4*4) = v;
            }
        }
        __syncthreads();

        float oc[2][2][4];
        #pragma unroll
        for (int mt = 0; mt < 2; mt++)
            #pragma unroll
            for (int nt = 0; nt < 2; nt++)
                #pragma unroll
                for (int j = 0; j < 4; j++) oc[mt][nt][j] = 0.f;

        #pragma unroll 1
        for (int di = 0; di < 9; di++) {
            const float* vrow = kv + (wid + di)*(TC_*CPAD2);
            #pragma unroll
            for (int kst = 0; kst < 3; kst++) {
                float bb[2][2];
                #pragma unroll
                for (int nt = 0; nt < 2; nt++) {
                    int i0 = nt*8 + g;
                    int j0 = kst*8 + tg;
                    int dj0 = j0 - i0;
                    int dj1 = dj0 + 4;
                    bb[nt][0] = ((unsigned)dj0 <= 8u) ? sa[i0*84 + di*9 + dj0] : 0.f;
                    bb[nt][1] = ((unsigned)dj1 <= 8u) ? sa[i0*84 + di*9 + dj1] : 0.f;
                }
                #pragma unroll
                for (int mt = 0; mt < 2; mt++) {
                    float av[4];
                    av[0] = vrow[(kst*8 + tg)    *CPAD2 + mt*16 + g];
                    av[1] = vrow[(kst*8 + tg)    *CPAD2 + mt*16 + g + 8];
                    av[2] = vrow[(kst*8 + tg + 4)*CPAD2 + mt*16 + g];
                    av[3] = vrow[(kst*8 + tg + 4)*CPAD2 + mt*16 + g + 8];
                    mma_tf32(oc[mt][0], av, bb[0][0], bb[0][1]);
                    mma_tf32(oc[mt][1], av, bb[1][0], bb[1][1]);
                }
            }
        }

        // store this pass's 32 channels
        #pragma unroll
        for (int nt = 0; nt < 2; nt++) {
            int pxl = nt*8 + 2*tg;
            float is0 = sinv[wid*16 + pxl];
            float is1 = sinv[wid*16 + pxl + 1];
            int w = w0 + pxl;
            #pragma unroll
            for (int mt = 0; mt < 2; mt++) {
                int c  = vp*32 + mt*16 + g;
                float* ob0 = out + ((size_t)(n*C_ + c)*H_ + h)*W_;
                float* ob1 = out + ((size_t)(n*C_ + c + 8)*H_ + h)*W_;
                if (w < W_) {
                    ob0[w] = oc[mt][nt][0] * is0;
                    ob1[w] = oc[mt][nt][2] * is0;
                }
                if (w + 1 < W_) {
                    ob0[w+1] = oc[mt][nt][1] * is1;
                    ob1[w+1] = oc[mt][nt][3] * is1;
                }
            }
        }
    }
}

// ---------------- launch ------------------------------------------------------
extern "C" void kernel_launch(void* const* d_in, const int* in_sizes, int n_in,
                              void* d_out, int out_size)
{
    (void)in_sizes; (void)n_in; (void)out_size;
    const float* img  = (const float*)d_in[0];
    const float* wimg = (const float*)d_in[1];
    const float* wc   = (const float*)d_in[2];
    const float* gg   = (const float*)d_in[3];
    const float* bb   = (const float*)d_in[4];
    const float* mm   = (const float*)d_in[5];
    const float* vv   = (const float*)d_in[6];
    float* out = (float*)d_out;

    static int attr_set = 0;
    if (!attr_set) {
        cudaFuncSetAttribute(attn_kernel,
                             cudaFuncAttributeMaxDynamicSharedMemorySize, SMEM2_BYTES);
        cudaFuncSetAttribute(qkv_kernel,
                             cudaFuncAttributeMaxDynamicSharedMemorySize, QKV_SMEM);
        attr_set = 1;
    }

    prep_kernel<<<81, 256>>>(wc, gg, bb, mm, vv);

    dim3 qgrid(HW_/128, BN_);   // 175 x 6
    qkv_kernel<<<qgrid, 128, QKV_SMEM>>>(img, wimg);

    dim3 agrid((W_ + 15)/16, H_/8, BN_);   // 13 x 14 x 6
    attn_kernel<<<agrid, 256, SMEM2_BYTES>>>(out);
}

// round 12
// speedup vs baseline: 1.4634x; 1.0866x over previous
#include <cuda_runtime.h>
#include <cuda_fp16.h>
#include <math.h>

// Problem constants
#define H_    112
#define W_    200
#define HW_   (H_*W_)        // 22400
#define C_    64
#define BN_   6
#define PAD_  4
#define HP_   (H_ + 2*PAD_)  // 120
#define WP_   (W_ + 2*PAD_)  // 208
#define HPWP_ (HP_*WP_)      // 24960
#define QW_   208
#define NTAP  81

// tf32 round (rna), b32 destination
__device__ __forceinline__ float tf32r(float x) {
    unsigned u;
    asm("cvt.rna.tf32.f32 %0, %1;" : "=r"(u) : "f"(x));
    return __uint_as_float(u);
}

__device__ __forceinline__ void mma_tf32(float c[4], const float a[4], float b0, float b1) {
    const unsigned* A = (const unsigned*)a;
    asm("mma.sync.aligned.m16n8k8.row.col.f32.tf32.tf32.f32 "
        "{%0,%1,%2,%3}, {%4,%5,%6,%7}, {%8,%9}, {%0,%1,%2,%3};"
        : "+f"(c[0]), "+f"(c[1]), "+f"(c[2]), "+f"(c[3])
        : "r"(A[0]), "r"(A[1]), "r"(A[2]), "r"(A[3]),
          "r"(__float_as_uint(b0)), "r"(__float_as_uint(b1)));
}

// fp16 mma, fp32 accumulate: D[16px x 8col] += A[16px x 16ch] * B[16ch x 8col]
__device__ __forceinline__ void mma_f16(float c[4], const unsigned a[4],
                                        unsigned b0, unsigned b1) {
    asm("mma.sync.aligned.m16n8k16.row.col.f32.f16.f16.f32 "
        "{%0,%1,%2,%3}, {%4,%5,%6,%7}, {%8,%9}, {%0,%1,%2,%3};"
        : "+f"(c[0]), "+f"(c[1]), "+f"(c[2]), "+f"(c[3])
        : "r"(a[0]), "r"(a[1]), "r"(a[2]), "r"(a[3]), "r"(b0), "r"(b1));
}

// ---------------- scratch -----------------------------------------------------
__device__ unsigned g_qh  [BN_*H_*QW_*32];   // Q fp16, [n][h][w208][ch] (u32 = 2ch)
__device__ unsigned g_kph [BN_*HPWP_*32];    // K fp16, padded channel-last
__device__ float4   g_vpad[BN_*HPWP_*16];    // V fp32, padded channel-last (tf32 vals)
__device__ float4   g_Wf4 [5*8*4*32];        // conv weight A-frags: [l][k0][m0][lane]{4}
__device__ float    g_bf  [5*64];            // folded bias

// ---------------- prep: fine-grained, one store per thread --------------------
// idx ranges:
//   [0, 20480)              weight fragment floats
//   [20480, 20800)          bias
//   [20800, 143680)         K border uint4  (15360 px x 8)
//   [143680, 389440)        V border float4 (15360 px x 16)
//   [389440, 432448)        Q col-pad uint4 (5376 px x 8)
#define PREP_W0   20480
#define PREP_B0   20800
#define PREP_K0   143680
#define PREP_V0   389440
#define PREP_N    432448

__device__ __forceinline__ void border_px(int j, int& row, int& col) {
    if (j < 1664) {
        int r = j / 208;
        col = j - r * 208;
        row = (r < 4) ? r : (112 + r);
    } else {
        int k = j - 1664;
        row = 4 + (k >> 3);
        int c = k & 7;
        col = (c < 4) ? c : (200 + c);
    }
}

__global__ void prep_kernel(const float* __restrict__ wc, const float* __restrict__ gam,
                            const float* __restrict__ bet, const float* __restrict__ mu,
                            const float* __restrict__ var) {
    int idx = blockIdx.x * 256 + threadIdx.x;
    if (idx < PREP_W0) {
        int l  = idx >> 12;
        int r  = idx & 4095;
        int k0 = r >> 9;
        int r2 = r & 511;
        int m0 = r2 >> 7;
        int r3 = r2 & 127;
        int lane = r3 >> 2;
        int j    = r3 & 3;
        int g  = lane >> 2;
        int tg = lane & 3;
        int o  = m0*16 + g + ((j & 1) ? 8 : 0);
        int ci = k0*8 + tg + ((j >= 2) ? 4 : 0);
        float s = gam[l*64 + o] * rsqrtf(var[l*64 + o] + 1e-5f);
        ((float*)g_Wf4)[idx] = tf32r(s * wc[(l*64 + o)*64 + ci]);
    } else if (idx < PREP_B0) {
        int i = idx - PREP_W0;
        float s = gam[i] * rsqrtf(var[i] + 1e-5f);
        g_bf[i] = bet[i] - s * mu[i];
    } else if (idx < PREP_K0) {
        int it = idx - PREP_B0;
        int pxi = it >> 3, c8 = it & 7;
        int n = pxi / 2560, j = pxi - n*2560;
        int row, col; border_px(j, row, col);
        size_t px = (size_t)(n * HP_ + row) * WP_ + col;
        ((uint4*)(g_kph + px*32))[c8] = make_uint4(0, 0, 0, 0);
    } else if (idx < PREP_V0) {
        int it = idx - PREP_K0;
        int pxi = it >> 4, c4 = it & 15;
        int n = pxi / 2560, j = pxi - n*2560;
        int row, col; border_px(j, row, col);
        size_t px = (size_t)(n * HP_ + row) * WP_ + col;
        g_vpad[px*16 + c4] = make_float4(0.f, 0.f, 0.f, 0.f);
    } else if (idx < PREP_N) {
        int it = idx - PREP_V0;
        int pxi = it >> 3, c8 = it & 7;
        int n = pxi / (H_*8);
        int rr = pxi - n*(H_*8);
        int h = rr >> 3;
        int c = rr & 7;
        size_t px = (size_t)(n*H_ + h)*QW_ + 200 + c;
        ((uint4*)(g_qh + px*32))[c8] = make_uint4(0, 0, 0, 0);
    }
}

// ---------------- fused 5-layer QKV via tensor cores (round-8 core) ----------
#define XSTRIDE 40
#define BUF_F   (64*XSTRIDE)
#define QKV_SMEM (4*2*BUF_F*4)

__device__ __forceinline__ void stage_tile(const float* __restrict__ src, float* buf, int lane) {
    int ci0 = lane >> 3;
    int px4 = lane & 7;
    #pragma unroll
    for (int it = 0; it < 16; it++) {
        int ci = it*4 + ci0;
        float4 v = *(const float4*)(src + (size_t)ci*HW_ + px4*4);
        v.x = tf32r(v.x); v.y = tf32r(v.y); v.z = tf32r(v.z); v.w = tf32r(v.w);
        *(float4*)(buf + ci*XSTRIDE + px4*4) = v;
    }
}

__device__ __forceinline__ void layer_mma(const float* buf, int l, int lane, float c[4][4][4]) {
    int g = lane >> 2, tg = lane & 3;
    #pragma unroll
    for (int m = 0; m < 4; m++)
        #pragma unroll
        for (int nt = 0; nt < 4; nt++)
            #pragma unroll
            for (int j = 0; j < 4; j++) c[m][nt][j] = 0.f;

    const float4* wf = g_Wf4 + (size_t)l*8*4*32;
    #pragma unroll
    for (int k0 = 0; k0 < 8; k0++) {
        float4 a[4];
        #pragma unroll
        for (int m = 0; m < 4; m++)
            a[m] = __ldg(wf + (k0*4 + m)*32 + lane);
        #pragma unroll
        for (int nt = 0; nt < 4; nt++) {
            float b0 = buf[(k0*8 + tg)    *XSTRIDE + nt*8 + g];
            float b1 = buf[(k0*8 + tg + 4)*XSTRIDE + nt*8 + g];
            #pragma unroll
            for (int m = 0; m < 4; m++)
                mma_tf32(c[m][nt], (const float*)&a[m], b0, b1);
        }
    }
}

__device__ __forceinline__ void epi_smem(float c[4][4][4], float* bufo, int l, int lane) {
    int g = lane >> 2, tg = lane & 3;
    #pragma unroll
    for (int m = 0; m < 4; m++) {
        float b0 = g_bf[l*64 + m*16 + g];
        float b1 = g_bf[l*64 + m*16 + g + 8];
        #pragma unroll
        for (int nt = 0; nt < 4; nt++) {
            int px = nt*8 + 2*tg;
            bufo[(m*16 + g)    *XSTRIDE + px]     = tf32r(fmaxf(c[m][nt][0] + b0, 0.f));
            bufo[(m*16 + g)    *XSTRIDE + px + 1] = tf32r(fmaxf(c[m][nt][1] + b0, 0.f));
            bufo[(m*16 + g + 8)*XSTRIDE + px]     = tf32r(fmaxf(c[m][nt][2] + b1, 0.f));
            bufo[(m*16 + g + 8)*XSTRIDE + px + 1] = tf32r(fmaxf(c[m][nt][3] + b1, 0.f));
        }
    }
}

// fp32 (tf32-rounded) channel-last gmem epilogue — used for V
__device__ __forceinline__ void epi_gmem(float c[4][4][4], float* base, int l, int lane, int px0) {
    int g = lane >> 2, tg = lane & 3;
    float bs0[4], bs1[4];
    #pragma unroll
    for (int m = 0; m < 4; m++) {
        bs0[m] = g_bf[l*64 + m*16 + g];
        bs1[m] = g_bf[l*64 + m*16 + g + 8];
    }
    #pragma unroll
    for (int nt = 0; nt < 4; nt++) {
        #pragma unroll
        for (int j = 0; j < 2; j++) {
            int px = px0 + nt*8 + 2*tg + j;
            int h = px / W_;
            int w = px - h*W_;
            float* p = base + ((size_t)h*WP_ + w)*64;
            #pragma unroll
            for (int m = 0; m < 4; m++) {
                p[m*16 + g]     = tf32r(fmaxf(c[m][nt][j]     + bs0[m], 0.f));
                p[m*16 + g + 8] = tf32r(fmaxf(c[m][nt][2 + j] + bs1[m], 0.f));
            }
        }
    }
}

// fp16 channel-last gmem epilogue — used for Q and K
__device__ __forceinline__ void epi_gmem_h(float c[4][4][4], __half* base, int l, int lane, int px0) {
    int g = lane >> 2, tg = lane & 3;
    float bs0[4], bs1[4];
    #pragma unroll
    for (int m = 0; m < 4; m++) {
        bs0[m] = g_bf[l*64 + m*16 + g];
        bs1[m] = g_bf[l*64 + m*16 + g + 8];
    }
    #pragma unroll
    for (int nt = 0; nt < 4; nt++) {
        #pragma unroll
        for (int j = 0; j < 2; j++) {
            int px = px0 + nt*8 + 2*tg + j;
            int h = px / W_;
            int w = px - h*W_;
            __half* p = base + ((size_t)h*WP_ + w)*64;
            #pragma unroll
            for (int m = 0; m < 4; m++) {
                p[m*16 + g]     = __float2half_rn(fmaxf(c[m][nt][j]     + bs0[m], 0.f));
                p[m*16 + g + 8] = __float2half_rn(fmaxf(c[m][nt][2 + j] + bs1[m], 0.f));
            }
        }
    }
}

__global__ __launch_bounds__(128) void qkv_kernel(const float* __restrict__ img,
                                                  const float* __restrict__ wimg)
{
    extern __shared__ float xs[];
    const int tid = threadIdx.x;
    const int wid = tid >> 5;
    const int lane = tid & 31;
    const int n = blockIdx.y;
    const int px0 = (blockIdx.x*4 + wid) * 32;

    float* bufA = xs + wid * (2*BUF_F);
    float* bufB = bufA + BUF_F;
    float c[4][4][4];

    const float* wsrc = wimg + (size_t)n*C_*HW_ + px0;
    const float* isrc = img  + (size_t)n*C_*HW_ + px0;
    __half* qb = (__half*)g_qh  + (size_t)n*H_*QW_*64;
    __half* kb = (__half*)g_kph + (((size_t)n*HP_ + PAD_)*WP_ + PAD_)*64;
    float*  vb = (float*)g_vpad + (((size_t)n*HP_ + PAD_)*WP_ + PAD_)*64;

    stage_tile(wsrc, bufA, lane);  __syncwarp();
    layer_mma(bufA, 4, lane, c);   epi_gmem(c, vb, 4, lane, px0);
    layer_mma(bufA, 2, lane, c);   epi_smem(c, bufB, 2, lane);  __syncwarp();
    layer_mma(bufB, 3, lane, c);   epi_gmem_h(c, kb, 3, lane, px0);
    stage_tile(isrc, bufA, lane);  __syncwarp();
    layer_mma(bufA, 0, lane, c);   epi_smem(c, bufB, 0, lane);  __syncwarp();
    layer_mma(bufB, 1, lane, c);   epi_gmem_h(c, qb, 1, lane, px0);
}

// ---------------- attention: single-pass fp16 phase-1, tf32 phase-2 ----------
#define TR_   16
#define TC_   24
#define CPAD2 36                        // fp32 V tile: 32 ch + 4 pad (f32 units)
#define CPADH 36                        // fp16 K tile: 32 u32 (64 ch) + 4 pad (u32 units)
#define KV2_F  (TR_*TC_*36)             // 13824 words (f32 or u32 — same bytes)
#define SACC_F (8*16*84)                // 10752 f
#define SMEM2_F (KV2_F + SACC_F + 8*16)
#define SMEM2_BYTES (SMEM2_F*4)         // 98816 B -> 2 CTAs/SM

__device__ __forceinline__ void band_store(float* sa, float v, int px, int col, int di) {
    int dj = col - px;
    if ((unsigned)dj <= 8u)
        sa[px*84 + di*9 + dj] = v;
}

__global__ __launch_bounds__(256, 2) void attn_kernel(float* __restrict__ out)
{
    extern __shared__ float smem[];
    float*    kv  = smem;               // union: K fp16 [16][24][36 u32] / V fp32 [16][24][36]
    unsigned* kvu = (unsigned*)smem;
    float* sacc = smem + KV2_F;         // [8][16][84]
    float* sinv = sacc + SACC_F;        // [8][16]

    const int tid  = threadIdx.x;
    const int wid  = tid >> 5;
    const int lane = tid & 31;
    const int g    = lane >> 2;
    const int tg   = lane & 3;
    const int n  = blockIdx.z;
    const int h0 = blockIdx.y * 8;
    const int w0 = blockIdx.x * 16;
    const int h  = h0 + wid;

    // ---- stage full 64-ch fp16 K tile (single pass) ----
    {
        const uint4* kb = (const uint4*)(g_kph + (size_t)(n*HP_ + h0) * WP_ * 32);
        for (int i = tid; i < TR_*TC_*8; i += 256) {
            int px = i >> 3, c8 = i & 7;
            int r = px / TC_, c = px - r*TC_;
            int pcol = w0 + c; if (pcol > 207) pcol = 207;
            uint4 v = kb[((size_t)r*WP_ + pcol)*8 + c8];
            *(uint4*)(kvu + px*CPADH + c8*4) = v;
        }
    }

    // ---- Q fp16 A-fragments: 4 k-steps of 16 ch ----
    unsigned qa[4][4];
    {
        const unsigned* q0 = g_qh + ((size_t)(n*H_ + h)*QW_ + (w0 + g))     * 32;
        const unsigned* q1 = g_qh + ((size_t)(n*H_ + h)*QW_ + (w0 + g + 8)) * 32;
        #pragma unroll
        for (int ks = 0; ks < 4; ks++) {
            qa[ks][0] = q0[ks*8 + tg];
            qa[ks][1] = q1[ks*8 + tg];
            qa[ks][2] = q0[ks*8 + tg + 4];
            qa[ks][3] = q1[ks*8 + tg + 4];
        }
    }
    __syncthreads();

    float* sa = sacc + wid*(16*84);

    // ---- phase 1: similarity, fp16 mma, one 64-ch pass, direct band store ----
    #pragma unroll 1
    for (int di = 0; di < 9; di++) {
        float c0[3][4];
        #pragma unroll
        for (int nt = 0; nt < 3; nt++)
            #pragma unroll
            for (int j = 0; j < 4; j++) c0[nt][j] = 0.f;
        const unsigned* krow = kvu + (wid + di)*(TC_*CPADH);
        #pragma unroll
        for (int nt = 0; nt < 3; nt++) {
            const unsigned* kc = krow + (nt*8 + g)*CPADH;
            #pragma unroll
            for (int ks = 0; ks < 4; ks++) {
                unsigned b0 = kc[ks*8 + tg];
                unsigned b1 = kc[ks*8 + tg + 4];
                mma_f16(c0[nt], qa[ks], b0, b1);
            }
        }
        #pragma unroll
        for (int nt = 0; nt < 3; nt++) {
            int colb = nt*8 + 2*tg;
            band_store(sa, c0[nt][0], g,     colb,     di);
            band_store(sa, c0[nt][1], g,     colb + 1, di);
            band_store(sa, c0[nt][2], g + 8, colb,     di);
            band_store(sa, c0[nt][3], g + 8, colb + 1, di);
        }
    }
    __syncwarp();

    // ---- softmax (2 lanes per px) ----
    {
        int px   = lane & 15;
        int half = lane >> 4;
        float* sp = sa + px*84;
        int t0 = half * 41;
        int tc = 41 - half;
        float mx = -1e30f;
        for (int t = 0; t < tc; t++) {
            float v = sp[t0 + t] * 0.125f;
            mx = fmaxf(mx, v);
        }
        mx = fmaxf(mx, __shfl_xor_sync(0xffffffffu, mx, 16));
        float sum = 0.f;
        for (int t = 0; t < tc; t++) {
            float e = __expf(sp[t0 + t] * 0.125f - mx);
            sum += e;
            sp[t0 + t] = tf32r(e);
        }
        sum += __shfl_xor_sync(0xffffffffu, sum, 16);
        if (half == 0) sinv[wid*16 + px] = 1.f / sum;
    }

    // ---- phase 2: weighting, tf32, two 32-channel passes (proven R10) ----
    #pragma unroll 1
    for (int vp = 0; vp < 2; vp++) {
        __syncthreads();
        {
            const float4* vb = g_vpad + (size_t)(n*HP_ + h0) * WP_ * 16;
            for (int i = tid; i < TR_*TC_*8; i += 256) {
                int px = i >> 3, c4 = i & 7;
                int r = px / TC_, c = px - r*TC_;
                int pcol = w0 + c; if (pcol > 207) pcol = 207;
                float4 v = vb[((size_t)r*WP_ + pcol)*16 + vp*8 + c4];
                *(float4*)(kv + px*CPAD2 + c4*4) = v;
            }
        }
        __syncthreads();

        float oc[2][2][4];
        #pragma unroll
        for (int mt = 0; mt < 2; mt++)
            #pragma unroll
            for (int nt = 0; nt < 2; nt++)
                #pragma unroll
                for (int j = 0; j < 4; j++) oc[mt][nt][j] = 0.f;

        #pragma unroll 1
        for (int di = 0; di < 9; di++) {
            const float* vrow = kv + (wid + di)*(TC_*CPAD2);
            #pragma unroll
            for (int kst = 0; kst < 3; kst++) {
                float bb[2][2];
                #pragma unroll
                for (int nt = 0; nt < 2; nt++) {
                    int i0 = nt*8 + g;
                    int j0 = kst*8 + tg;
                    int dj0 = j0 - i0;
                    int dj1 = dj0 + 4;
                    bb[nt][0] = ((unsigned)dj0 <= 8u) ? sa[i0*84 + di*9 + dj0] : 0.f;
                    bb[nt][1] = ((unsigned)dj1 <= 8u) ? sa[i0*84 + di*9 + dj1] : 0.f;
                }
                #pragma unroll
                for (int mt = 0; mt < 2; mt++) {
                    float av[4];
                    av[0] = vrow[(kst*8 + tg)    *CPAD2 + mt*16 + g];
                    av[1] = vrow[(kst*8 + tg)    *CPAD2 + mt*16 + g + 8];
                    av[2] = vrow[(kst*8 + tg + 4)*CPAD2 + mt*16 + g];
                    av[3] = vrow[(kst*8 + tg + 4)*CPAD2 + mt*16 + g + 8];
                    mma_tf32(oc[mt][0], av, bb[0][0], bb[0][1]);
                    mma_tf32(oc[mt][1], av, bb[1][0], bb[1][1]);
                }
            }
        }

        // store this pass's 32 channels
        #pragma unroll
        for (int nt = 0; nt < 2; nt++) {
            int pxl = nt*8 + 2*tg;
            float is0 = sinv[wid*16 + pxl];
            float is1 = sinv[wid*16 + pxl + 1];
            int w = w0 + pxl;
            #pragma unroll
            for (int mt = 0; mt < 2; mt++) {
                int c  = vp*32 + mt*16 + g;
                float* ob0 = out + ((size_t)(n*C_ + c)*H_ + h)*W_;
                float* ob1 = out + ((size_t)(n*C_ + c + 8)*H_ + h)*W_;
                if (w < W_) {
                    ob0[w] = oc[mt][nt][0] * is0;
                    ob1[w] = oc[mt][nt][2] * is0;
                }
                if (w + 1 < W_) {
                    ob0[w+1] = oc[mt][nt][1] * is1;
                    ob1[w+1] = oc[mt][nt][3] * is1;
                }
            }
        }
    }
}

// ---------------- launch ------------------------------------------------------
extern "C" void kernel_launch(void* const* d_in, const int* in_sizes, int n_in,
                              void* d_out, int out_size)
{
    (void)in_sizes; (void)n_in; (void)out_size;
    const float* img  = (const float*)d_in[0];
    const float* wimg = (const float*)d_in[1];
    const float* wc   = (const float*)d_in[2];
    const float* gg   = (const float*)d_in[3];
    const float* bb   = (const float*)d_in[4];
    const float* mm   = (const float*)d_in[5];
    const float* vv   = (const float*)d_in[6];
    float* out = (float*)d_out;

    static int attr_set = 0;
    if (!attr_set) {
        cudaFuncSetAttribute(attn_kernel,
                             cudaFuncAttributeMaxDynamicSharedMemorySize, SMEM2_BYTES);
        cudaFuncSetAttribute(qkv_kernel,
                             cudaFuncAttributeMaxDynamicSharedMemorySize, QKV_SMEM);
        attr_set = 1;
    }

    prep_kernel<<<(PREP_N + 255)/256, 256>>>(wc, gg, bb, mm, vv);

    dim3 qgrid(HW_/128, BN_);   // 175 x 6
    qkv_kernel<<<qgrid, 128, QKV_SMEM>>>(img, wimg);

    dim3 agrid((W_ + 15)/16, H_/8, BN_);   // 13 x 14 x 6
    attn_kernel<<<agrid, 256, SMEM2_BYTES>>>(out);
}

// round 13
// speedup vs baseline: 1.6755x; 1.1449x over previous
#include <cuda_runtime.h>
#include <cuda_fp16.h>
#include <math.h>

// Problem constants
#define H_    112
#define W_    200
#define HW_   (H_*W_)        // 22400
#define C_    64
#define BN_   6
#define PAD_  4
#define HP_   (H_ + 2*PAD_)  // 120
#define WP_   (W_ + 2*PAD_)  // 208
#define HPWP_ (HP_*WP_)      // 24960
#define QW_   208
#define NTAP  81

// tf32 round (rna), b32 destination
__device__ __forceinline__ float tf32r(float x) {
    unsigned u;
    asm("cvt.rna.tf32.f32 %0, %1;" : "=r"(u) : "f"(x));
    return __uint_as_float(u);
}

__device__ __forceinline__ void mma_tf32(float c[4], const float a[4], float b0, float b1) {
    const unsigned* A = (const unsigned*)a;
    asm("mma.sync.aligned.m16n8k8.row.col.f32.tf32.tf32.f32 "
        "{%0,%1,%2,%3}, {%4,%5,%6,%7}, {%8,%9}, {%0,%1,%2,%3};"
        : "+f"(c[0]), "+f"(c[1]), "+f"(c[2]), "+f"(c[3])
        : "r"(A[0]), "r"(A[1]), "r"(A[2]), "r"(A[3]),
          "r"(__float_as_uint(b0)), "r"(__float_as_uint(b1)));
}

// fp16 mma, fp32 accumulate
__device__ __forceinline__ void mma_f16(float c[4], const unsigned a[4],
                                        unsigned b0, unsigned b1) {
    asm("mma.sync.aligned.m16n8k16.row.col.f32.f16.f16.f32 "
        "{%0,%1,%2,%3}, {%4,%5,%6,%7}, {%8,%9}, {%0,%1,%2,%3};"
        : "+f"(c[0]), "+f"(c[1]), "+f"(c[2]), "+f"(c[3])
        : "r"(a[0]), "r"(a[1]), "r"(a[2]), "r"(a[3]), "r"(b0), "r"(b1));
}

// ---------------- scratch -----------------------------------------------------
__device__ unsigned g_qh  [BN_*H_*QW_*32];   // Q fp16, [n][h][w208][ch] (u32 = 2ch)
__device__ unsigned g_kph [BN_*HPWP_*32];    // K fp16, padded channel-last
__device__ unsigned g_vph [BN_*HPWP_*32];    // V fp16, padded channel-last
__device__ float4   g_Wf4 [5*8*4*32];        // conv weight A-frags: [l][k0][m0][lane]{4}
__device__ float    g_bf  [5*64];            // folded bias

// ---------------- prep: fine-grained, one store per thread --------------------
// idx ranges:
//   [0, 20480)              weight fragment floats
//   [20480, 20800)          bias
//   [20800, 143680)         K border uint4  (15360 px x 8)
//   [143680, 266560)        V border uint4  (15360 px x 8)
//   [266560, 309568)        Q col-pad uint4 (5376 px x 8)
#define PREP_W0   20480
#define PREP_B0   20800
#define PREP_K0   143680
#define PREP_V0   266560
#define PREP_N    309568

__device__ __forceinline__ void border_px(int j, int& row, int& col) {
    if (j < 1664) {
        int r = j / 208;
        col = j - r * 208;
        row = (r < 4) ? r : (112 + r);
    } else {
        int k = j - 1664;
        row = 4 + (k >> 3);
        int c = k & 7;
        col = (c < 4) ? c : (200 + c);
    }
}

__global__ void prep_kernel(const float* __restrict__ wc, const float* __restrict__ gam,
                            const float* __restrict__ bet, const float* __restrict__ mu,
                            const float* __restrict__ var) {
    int idx = blockIdx.x * 256 + threadIdx.x;
    if (idx < PREP_W0) {
        int l  = idx >> 12;
        int r  = idx & 4095;
        int k0 = r >> 9;
        int r2 = r & 511;
        int m0 = r2 >> 7;
        int r3 = r2 & 127;
        int lane = r3 >> 2;
        int j    = r3 & 3;
        int g  = lane >> 2;
        int tg = lane & 3;
        int o  = m0*16 + g + ((j & 1) ? 8 : 0);
        int ci = k0*8 + tg + ((j >= 2) ? 4 : 0);
        float s = gam[l*64 + o] * rsqrtf(var[l*64 + o] + 1e-5f);
        ((float*)g_Wf4)[idx] = tf32r(s * wc[(l*64 + o)*64 + ci]);
    } else if (idx < PREP_B0) {
        int i = idx - PREP_W0;
        float s = gam[i] * rsqrtf(var[i] + 1e-5f);
        g_bf[i] = bet[i] - s * mu[i];
    } else if (idx < PREP_K0) {
        int it = idx - PREP_B0;
        int pxi = it >> 3, c8 = it & 7;
        int n = pxi / 2560, j = pxi - n*2560;
        int row, col; border_px(j, row, col);
        size_t px = (size_t)(n * HP_ + row) * WP_ + col;
        ((uint4*)(g_kph + px*32))[c8] = make_uint4(0, 0, 0, 0);
    } else if (idx < PREP_V0) {
        int it = idx - PREP_K0;
        int pxi = it >> 3, c8 = it & 7;
        int n = pxi / 2560, j = pxi - n*2560;
        int row, col; border_px(j, row, col);
        size_t px = (size_t)(n * HP_ + row) * WP_ + col;
        ((uint4*)(g_vph + px*32))[c8] = make_uint4(0, 0, 0, 0);
    } else if (idx < PREP_N) {
        int it = idx - PREP_V0;
        int pxi = it >> 3, c8 = it & 7;
        int n = pxi / (H_*8);
        int rr = pxi - n*(H_*8);
        int h = rr >> 3;
        int c = rr & 7;
        size_t px = (size_t)(n*H_ + h)*QW_ + 200 + c;
        ((uint4*)(g_qh + px*32))[c8] = make_uint4(0, 0, 0, 0);
    }
}

// ---------------- fused 5-layer QKV via tensor cores (round-8 core) ----------
#define XSTRIDE 40
#define BUF_F   (64*XSTRIDE)
#define QKV_SMEM (4*2*BUF_F*4)

__device__ __forceinline__ void stage_tile(const float* __restrict__ src, float* buf, int lane) {
    int ci0 = lane >> 3;
    int px4 = lane & 7;
    #pragma unroll
    for (int it = 0; it < 16; it++) {
        int ci = it*4 + ci0;
        float4 v = *(const float4*)(src + (size_t)ci*HW_ + px4*4);
        v.x = tf32r(v.x); v.y = tf32r(v.y); v.z = tf32r(v.z); v.w = tf32r(v.w);
        *(float4*)(buf + ci*XSTRIDE + px4*4) = v;
    }
}

__device__ __forceinline__ void layer_mma(const float* buf, int l, int lane, float c[4][4][4]) {
    int g = lane >> 2, tg = lane & 3;
    #pragma unroll
    for (int m = 0; m < 4; m++)
        #pragma unroll
        for (int nt = 0; nt < 4; nt++)
            #pragma unroll
            for (int j = 0; j < 4; j++) c[m][nt][j] = 0.f;

    const float4* wf = g_Wf4 + (size_t)l*8*4*32;
    #pragma unroll
    for (int k0 = 0; k0 < 8; k0++) {
        float4 a[4];
        #pragma unroll
        for (int m = 0; m < 4; m++)
            a[m] = __ldg(wf + (k0*4 + m)*32 + lane);
        #pragma unroll
        for (int nt = 0; nt < 4; nt++) {
            float b0 = buf[(k0*8 + tg)    *XSTRIDE + nt*8 + g];
            float b1 = buf[(k0*8 + tg + 4)*XSTRIDE + nt*8 + g];
            #pragma unroll
            for (int m = 0; m < 4; m++)
                mma_tf32(c[m][nt], (const float*)&a[m], b0, b1);
        }
    }
}

__device__ __forceinline__ void epi_smem(float c[4][4][4], float* bufo, int l, int lane) {
    int g = lane >> 2, tg = lane & 3;
    #pragma unroll
    for (int m = 0; m < 4; m++) {
        float b0 = g_bf[l*64 + m*16 + g];
        float b1 = g_bf[l*64 + m*16 + g + 8];
        #pragma unroll
        for (int nt = 0; nt < 4; nt++) {
            int px = nt*8 + 2*tg;
            bufo[(m*16 + g)    *XSTRIDE + px]     = tf32r(fmaxf(c[m][nt][0] + b0, 0.f));
            bufo[(m*16 + g)    *XSTRIDE + px + 1] = tf32r(fmaxf(c[m][nt][1] + b0, 0.f));
            bufo[(m*16 + g + 8)*XSTRIDE + px]     = tf32r(fmaxf(c[m][nt][2] + b1, 0.f));
            bufo[(m*16 + g + 8)*XSTRIDE + px + 1] = tf32r(fmaxf(c[m][nt][3] + b1, 0.f));
        }
    }
}

// fp16 channel-last gmem epilogue — used for Q, K, and V
__device__ __forceinline__ void epi_gmem_h(float c[4][4][4], __half* base, int l, int lane, int px0) {
    int g = lane >> 2, tg = lane & 3;
    float bs0[4], bs1[4];
    #pragma unroll
    for (int m = 0; m < 4; m++) {
        bs0[m] = g_bf[l*64 + m*16 + g];
        bs1[m] = g_bf[l*64 + m*16 + g + 8];
    }
    #pragma unroll
    for (int nt = 0; nt < 4; nt++) {
        #pragma unroll
        for (int j = 0; j < 2; j++) {
            int px = px0 + nt*8 + 2*tg + j;
            int h = px / W_;
            int w = px - h*W_;
            __half* p = base + ((size_t)h*WP_ + w)*64;
            #pragma unroll
            for (int m = 0; m < 4; m++) {
                p[m*16 + g]     = __float2half_rn(fmaxf(c[m][nt][j]     + bs0[m], 0.f));
                p[m*16 + g + 8] = __float2half_rn(fmaxf(c[m][nt][2 + j] + bs1[m], 0.f));
            }
        }
    }
}

__global__ __launch_bounds__(128) void qkv_kernel(const float* __restrict__ img,
                                                  const float* __restrict__ wimg)
{
    extern __shared__ float xs[];
    const int tid = threadIdx.x;
    const int wid = tid >> 5;
    const int lane = tid & 31;
    const int n = blockIdx.y;
    const int px0 = (blockIdx.x*4 + wid) * 32;

    float* bufA = xs + wid * (2*BUF_F);
    float* bufB = bufA + BUF_F;
    float c[4][4][4];

    const float* wsrc = wimg + (size_t)n*C_*HW_ + px0;
    const float* isrc = img  + (size_t)n*C_*HW_ + px0;
    __half* qb = (__half*)g_qh  + (size_t)n*H_*QW_*64;
    __half* kb = (__half*)g_kph + (((size_t)n*HP_ + PAD_)*WP_ + PAD_)*64;
    __half* vb = (__half*)g_vph + (((size_t)n*HP_ + PAD_)*WP_ + PAD_)*64;

    stage_tile(wsrc, bufA, lane);  __syncwarp();
    layer_mma(bufA, 4, lane, c);   epi_gmem_h(c, vb, 4, lane, px0);
    layer_mma(bufA, 2, lane, c);   epi_smem(c, bufB, 2, lane);  __syncwarp();
    layer_mma(bufB, 3, lane, c);   epi_gmem_h(c, kb, 3, lane, px0);
    stage_tile(isrc, bufA, lane);  __syncwarp();
    layer_mma(bufA, 0, lane, c);   epi_smem(c, bufB, 0, lane);  __syncwarp();
    layer_mma(bufB, 1, lane, c);   epi_gmem_h(c, qb, 1, lane, px0);
}

// ---------------- attention: fp16 K/V tiles, single-pass both phases ---------
#define TR_   16
#define TC_   24
#define CPADH 36                        // 32 u32 (64 fp16 ch) + 4 pad, per px
#define KV2_F  (TR_*TC_*36)             // 13824 words
#define SACC_F (8*16*84)                // 10752 f
#define SMEM2_F (KV2_F + SACC_F + 8*16)
#define SMEM2_BYTES (SMEM2_F*4)         // 98816 B -> 2 CTAs/SM

__device__ __forceinline__ void band_store(float* sa, float v, int px, int col, int di) {
    int dj = col - px;
    if ((unsigned)dj <= 8u)
        sa[px*84 + di*9 + dj] = v;
}

__global__ __launch_bounds__(256, 2) void attn_kernel(float* __restrict__ out)
{
    extern __shared__ float smem[];
    unsigned* kvu = (unsigned*)smem;    // fp16 tile [16 rows][24 cols][36 u32]
    float* sacc = smem + KV2_F;         // [8][16][84]
    float* sinv = sacc + SACC_F;        // [8][16]

    const int tid  = threadIdx.x;
    const int wid  = tid >> 5;
    const int lane = tid & 31;
    const int g    = lane >> 2;
    const int tg   = lane & 3;
    const int n  = blockIdx.z;
    const int h0 = blockIdx.y * 8;
    const int w0 = blockIdx.x * 16;
    const int h  = h0 + wid;

    // ---- stage full 64-ch fp16 K tile ----
    {
        const uint4* kb = (const uint4*)(g_kph + (size_t)(n*HP_ + h0) * WP_ * 32);
        for (int i = tid; i < TR_*TC_*8; i += 256) {
            int px = i >> 3, c8 = i & 7;
            int r = px / TC_, c = px - r*TC_;
            int pcol = w0 + c; if (pcol > 207) pcol = 207;
            uint4 v = kb[((size_t)r*WP_ + pcol)*8 + c8];
            *(uint4*)(kvu + px*CPADH + c8*4) = v;
        }
    }

    // ---- Q fp16 A-fragments: 4 k-steps of 16 ch ----
    unsigned qa[4][4];
    {
        const unsigned* q0 = g_qh + ((size_t)(n*H_ + h)*QW_ + (w0 + g))     * 32;
        const unsigned* q1 = g_qh + ((size_t)(n*H_ + h)*QW_ + (w0 + g + 8)) * 32;
        #pragma unroll
        for (int ks = 0; ks < 4; ks++) {
            qa[ks][0] = q0[ks*8 + tg];
            qa[ks][1] = q1[ks*8 + tg];
            qa[ks][2] = q0[ks*8 + tg + 4];
            qa[ks][3] = q1[ks*8 + tg + 4];
        }
    }
    __syncthreads();

    float* sa = sacc + wid*(16*84);

    // ---- phase 1: similarity, fp16 mma, direct band store ----
    #pragma unroll 1
    for (int di = 0; di < 9; di++) {
        float c0[3][4];
        #pragma unroll
        for (int nt = 0; nt < 3; nt++)
            #pragma unroll
            for (int j = 0; j < 4; j++) c0[nt][j] = 0.f;
        const unsigned* krow = kvu + (wid + di)*(TC_*CPADH);
        #pragma unroll
        for (int nt = 0; nt < 3; nt++) {
            const unsigned* kc = krow + (nt*8 + g)*CPADH;
            #pragma unroll
            for (int ks = 0; ks < 4; ks++) {
                unsigned b0 = kc[ks*8 + tg];
                unsigned b1 = kc[ks*8 + tg + 4];
                mma_f16(c0[nt], qa[ks], b0, b1);
            }
        }
        #pragma unroll
        for (int nt = 0; nt < 3; nt++) {
            int colb = nt*8 + 2*tg;
            band_store(sa, c0[nt][0], g,     colb,     di);
            band_store(sa, c0[nt][1], g,     colb + 1, di);
            band_store(sa, c0[nt][2], g + 8, colb,     di);
            band_store(sa, c0[nt][3], g + 8, colb + 1, di);
        }
    }
    __syncwarp();

    // ---- softmax (2 lanes per px) ----
    {
        int px   = lane & 15;
        int half = lane >> 4;
        float* sp = sa + px*84;
        int t0 = half * 41;
        int tc = 41 - half;
        float mx = -1e30f;
        for (int t = 0; t < tc; t++) {
            float v = sp[t0 + t] * 0.125f;
            mx = fmaxf(mx, v);
        }
        mx = fmaxf(mx, __shfl_xor_sync(0xffffffffu, mx, 16));
        float sum = 0.f;
        for (int t = 0; t < tc; t++) {
            float e = __expf(sp[t0 + t] * 0.125f - mx);
            sum += e;
            sp[t0 + t] = tf32r(e);
        }
        sum += __shfl_xor_sync(0xffffffffu, sum, 16);
        if (half == 0) sinv[wid*16 + px] = 1.f / sum;
    }
    __syncthreads();   // all warps done with K tile + softmax before V overwrite

    // ---- stage full 64-ch fp16 V tile ----
    {
        const uint4* vb = (const uint4*)(g_vph + (size_t)(n*HP_ + h0) * WP_ * 32);
        for (int i = tid; i < TR_*TC_*8; i += 256) {
            int px = i >> 3, c8 = i & 7;
            int r = px / TC_, c = px - r*TC_;
            int pcol = w0 + c; if (pcol > 207) pcol = 207;
            uint4 v = vb[((size_t)r*WP_ + pcol)*8 + c8];
            *(uint4*)(kvu + px*CPADH + c8*4) = v;
        }
    }
    __syncthreads();

    // ---- phase 2: weighting, tf32 mma, fp16 V, single pass over 64 ch ----
    float oc[4][2][4];
    #pragma unroll
    for (int mt = 0; mt < 4; mt++)
        #pragma unroll
        for (int nt = 0; nt < 2; nt++)
            #pragma unroll
            for (int j = 0; j < 4; j++) oc[mt][nt][j] = 0.f;

    #pragma unroll 1
    for (int di = 0; di < 9; di++) {
        const __half* vrow = (const __half*)(kvu + (wid + di)*(TC_*CPADH));
        #pragma unroll
        for (int kst = 0; kst < 3; kst++) {
            float bb[2][2];
            #pragma unroll
            for (int nt = 0; nt < 2; nt++) {
                int i0 = nt*8 + g;
                int j0 = kst*8 + tg;
                int dj0 = j0 - i0;
                int dj1 = dj0 + 4;
                bb[nt][0] = ((unsigned)dj0 <= 8u) ? sa[i0*84 + di*9 + dj0] : 0.f;
                bb[nt][1] = ((unsigned)dj1 <= 8u) ? sa[i0*84 + di*9 + dj1] : 0.f;
            }
            const __half* r0 = vrow + (kst*8 + tg)*72;
            const __half* r1 = vrow + (kst*8 + tg + 4)*72;
            #pragma unroll
            for (int mt = 0; mt < 4; mt++) {
                float av[4];
                av[0] = __half2float(r0[mt*16 + g]);
                av[1] = __half2float(r0[mt*16 + g + 8]);
                av[2] = __half2float(r1[mt*16 + g]);
                av[3] = __half2float(r1[mt*16 + g + 8]);
                mma_tf32(oc[mt][0], av, bb[0][0], bb[0][1]);
                mma_tf32(oc[mt][1], av, bb[1][0], bb[1][1]);
            }
        }
    }

    // ---- epilogue: scale by 1/sum, store NCHW, all 64 channels ----
    #pragma unroll
    for (int nt = 0; nt < 2; nt++) {
        int pxl = nt*8 + 2*tg;
        float is0 = sinv[wid*16 + pxl];
        float is1 = sinv[wid*16 + pxl + 1];
        int w = w0 + pxl;
        #pragma unroll
        for (int mt = 0; mt < 4; mt++) {
            int c  = mt*16 + g;
            float* ob0 = out + ((size_t)(n*C_ + c)*H_ + h)*W_;
            float* ob1 = out + ((size_t)(n*C_ + c + 8)*H_ + h)*W_;
            if (w < W_) {
                ob0[w] = oc[mt][nt][0] * is0;
                ob1[w] = oc[mt][nt][2] * is0;
            }
            if (w + 1 < W_) {
                ob0[w+1] = oc[mt][nt][1] * is1;
                ob1[w+1] = oc[mt][nt][3] * is1;
            }
        }
    }
}

// ---------------- launch ------------------------------------------------------
extern "C" void kernel_launch(void* const* d_in, const int* in_sizes, int n_in,
                              void* d_out, int out_size)
{
    (void)in_sizes; (void)n_in; (void)out_size;
    const float* img  = (const float*)d_in[0];
    const float* wimg = (const float*)d_in[1];
    const float* wc   = (const float*)d_in[2];
    const float* gg   = (const float*)d_in[3];
    const float* bb   = (const float*)d_in[4];
    const float* mm   = (const float*)d_in[5];
    const float* vv   = (const float*)d_in[6];
    float* out = (float*)d_out;

    static int attr_set = 0;
    if (!attr_set) {
        cudaFuncSetAttribute(attn_kernel,
                             cudaFuncAttributeMaxDynamicSharedMemorySize, SMEM2_BYTES);
        cudaFuncSetAttribute(qkv_kernel,
                             cudaFuncAttributeMaxDynamicSharedMemorySize, QKV_SMEM);
        attr_set = 1;
    }

    prep_kernel<<<(PREP_N + 255)/256, 256>>>(wc, gg, bb, mm, vv);

    dim3 qgrid(HW_/128, BN_);   // 175 x 6
    qkv_kernel<<<qgrid, 128, QKV_SMEM>>>(img, wimg);

    dim3 agrid((W_ + 15)/16, H_/8, BN_);   // 13 x 14 x 6
    attn_kernel<<<agrid, 256, SMEM2_BYTES>>>(out);
}

// round 14
// speedup vs baseline: 1.8710x; 1.1167x over previous
#include <cuda_runtime.h>
#include <cuda_fp16.h>
#include <math.h>

// Problem constants
#define H_    112
#define W_    200
#define HW_   (H_*W_)        // 22400
#define C_    64
#define BN_   6
#define PAD_  4
#define HP_   (H_ + 2*PAD_)  // 120
#define WP_   (W_ + 2*PAD_)  // 208
#define HPWP_ (HP_*WP_)      // 24960
#define QW_   208
#define NTAP  81

// tf32 round (rna), b32 destination
__device__ __forceinline__ float tf32r(float x) {
    unsigned u;
    asm("cvt.rna.tf32.f32 %0, %1;" : "=r"(u) : "f"(x));
    return __uint_as_float(u);
}

__device__ __forceinline__ void mma_tf32(float c[4], const float a[4], float b0, float b1) {
    const unsigned* A = (const unsigned*)a;
    asm("mma.sync.aligned.m16n8k8.row.col.f32.tf32.tf32.f32 "
        "{%0,%1,%2,%3}, {%4,%5,%6,%7}, {%8,%9}, {%0,%1,%2,%3};"
        : "+f"(c[0]), "+f"(c[1]), "+f"(c[2]), "+f"(c[3])
        : "r"(A[0]), "r"(A[1]), "r"(A[2]), "r"(A[3]),
          "r"(__float_as_uint(b0)), "r"(__float_as_uint(b1)));
}

// fp16 mma, fp32 accumulate
__device__ __forceinline__ void mma_f16(float c[4], const unsigned a[4],
                                        unsigned b0, unsigned b1) {
    asm("mma.sync.aligned.m16n8k16.row.col.f32.f16.f16.f32 "
        "{%0,%1,%2,%3}, {%4,%5,%6,%7}, {%8,%9}, {%0,%1,%2,%3};"
        : "+f"(c[0]), "+f"(c[1]), "+f"(c[2]), "+f"(c[3])
        : "r"(a[0]), "r"(a[1]), "r"(a[2]), "r"(a[3]), "r"(b0), "r"(b1));
}

__device__ __forceinline__ unsigned pack2h(float lo, float hi) {
    __half2 h = __floats2half2_rn(lo, hi);   // .x = lo -> low 16 bits
    return *reinterpret_cast<unsigned*>(&h);
}

// ---------------- scratch -----------------------------------------------------
__device__ unsigned g_qh  [BN_*H_*QW_*32];   // Q fp16, [n][h][w208][ch] (u32 = 2ch)
__device__ unsigned g_kph [BN_*HPWP_*32];    // K fp16, padded channel-last
__device__ unsigned g_vph [BN_*HPWP_*32];    // V fp16, padded channel-last
__device__ uint4    g_Whf [5*4*4*32];        // fp16 weight A-frags: [l][ks][m][lane]
__device__ float    g_bf  [5*64];            // folded bias

// ---------------- prep: fine-grained, one store per thread --------------------
// idx ranges:
//   [0, 10240)              weight fragment u32s (fp16 pairs)
//   [10240, 10560)          bias
//   [10560, 133440)         K border uint4  (15360 px x 8)
//   [133440, 256320)        V border uint4  (15360 px x 8)
//   [256320, 299328)        Q col-pad uint4 (5376 px x 8)
#define PREP_W0   10240
#define PREP_B0   10560
#define PREP_K0   133440
#define PREP_V0   256320
#define PREP_N    299328

__device__ __forceinline__ void border_px(int j, int& row, int& col) {
    if (j < 1664) {
        int r = j / 208;
        col = j - r * 208;
        row = (r < 4) ? r : (112 + r);
    } else {
        int k = j - 1664;
        row = 4 + (k >> 3);
        int c = k & 7;
        col = (c < 4) ? c : (200 + c);
    }
}

__global__ void prep_kernel(const float* __restrict__ wc, const float* __restrict__ gam,
                            const float* __restrict__ bet, const float* __restrict__ mu,
                            const float* __restrict__ var) {
    int idx = blockIdx.x * 256 + threadIdx.x;
    if (idx < PREP_W0) {
        // u32 layout: [l][ks][m][lane][j]  (j = u32 within uint4)
        int l    = idx >> 11;
        int r    = idx & 2047;
        int ks   = r >> 9;
        int m    = (r >> 7) & 3;
        int lane = (r >> 2) & 31;
        int j    = r & 3;
        int g  = lane >> 2;
        int tg = lane & 3;
        int o  = m*16 + g + ((j & 1) ? 8 : 0);
        int k0 = ks*16 + 2*tg + ((j >= 2) ? 8 : 0);
        float s = gam[l*64 + o] * rsqrtf(var[l*64 + o] + 1e-5f);
        float w0 = s * wc[(l*64 + o)*64 + k0];
        float w1 = s * wc[(l*64 + o)*64 + k0 + 1];
        ((unsigned*)g_Whf)[idx] = pack2h(w0, w1);
    } else if (idx < PREP_B0) {
        int i = idx - PREP_W0;
        float s = gam[i] * rsqrtf(var[i] + 1e-5f);
        g_bf[i] = bet[i] - s * mu[i];
    } else if (idx < PREP_K0) {
        int it = idx - PREP_B0;
        int pxi = it >> 3, c8 = it & 7;
        int n = pxi / 2560, j = pxi - n*2560;
        int row, col; border_px(j, row, col);
        size_t px = (size_t)(n * HP_ + row) * WP_ + col;
        ((uint4*)(g_kph + px*32))[c8] = make_uint4(0, 0, 0, 0);
    } else if (idx < PREP_V0) {
        int it = idx - PREP_K0;
        int pxi = it >> 3, c8 = it & 7;
        int n = pxi / 2560, j = pxi - n*2560;
        int row, col; border_px(j, row, col);
        size_t px = (size_t)(n * HP_ + row) * WP_ + col;
        ((uint4*)(g_vph + px*32))[c8] = make_uint4(0, 0, 0, 0);
    } else if (idx < PREP_N) {
        int it = idx - PREP_V0;
        int pxi = it >> 3, c8 = it & 7;
        int n = pxi / (H_*8);
        int rr = pxi - n*(H_*8);
        int h = rr >> 3;
        int c = rr & 7;
        size_t px = (size_t)(n*H_ + h)*QW_ + 200 + c;
        ((uint4*)(g_qh + px*32))[c8] = make_uint4(0, 0, 0, 0);
    }
}

// ---------------- fused 5-layer QKV, full fp16 tensor cores ------------------
// Per warp: 32 px, channel-last fp16 activation buffers [32 px][36 u32].
// A = weight frags (gmem, L1-hot), B = activations (smem, bank-free: 4g+tg).
#define XW     36
#define XBUF_U (32*XW)                 // 1152 u32 per buffer
#define QKV_SMEM (4*2*XBUF_U*4)        // 36864 B

// NCHW fp32 -> channel-last fp16 smem tile (32 px x 64 ch)
__device__ __forceinline__ void stage_tile_h(const float* __restrict__ src,
                                             unsigned* xb, int lane) {
    int q = lane >> 3;          // 0..3  channel-pair sub-group
    int p = lane & 7;           // px group of 4
    #pragma unroll
    for (int it = 0; it < 8; it++) {
        int cp = it*4 + q;      // channel pair 0..31 (chs 2cp, 2cp+1)
        float4 a = *(const float4*)(src + (size_t)(2*cp)    *HW_ + p*4);
        float4 b = *(const float4*)(src + (size_t)(2*cp + 1)*HW_ + p*4);
        xb[(p*4 + 0)*XW + cp] = pack2h(a.x, b.x);
        xb[(p*4 + 1)*XW + cp] = pack2h(a.y, b.y);
        xb[(p*4 + 2)*XW + cp] = pack2h(a.z, b.z);
        xb[(p*4 + 3)*XW + cp] = pack2h(a.w, b.w);
    }
}

__device__ __forceinline__ void layer_mma_h(const unsigned* xb, int l, int lane,
                                            float c[4][4][4]) {
    int g = lane >> 2, tg = lane & 3;
    #pragma unroll
    for (int m = 0; m < 4; m++)
        #pragma unroll
        for (int nt = 0; nt < 4; nt++)
            #pragma unroll
            for (int j = 0; j < 4; j++) c[m][nt][j] = 0.f;

    const uint4* wf = g_Whf + (size_t)l*512;
    #pragma unroll
    for (int ks = 0; ks < 4; ks++) {
        uint4 a[4];
        #pragma unroll
        for (int m = 0; m < 4; m++)
            a[m] = __ldg(wf + (ks*4 + m)*32 + lane);
        #pragma unroll
        for (int nt = 0; nt < 4; nt++) {
            unsigned b0 = xb[(nt*8 + g)*XW + ks*8 + tg];
            unsigned b1 = xb[(nt*8 + g)*XW + ks*8 + tg + 4];
            #pragma unroll
            for (int m = 0; m < 4; m++)
                mma_f16(c[m][nt], (const unsigned*)&a[m], b0, b1);
        }
    }
}

// bias + relu -> fp16 channel-last smem buffer for next layer
__device__ __forceinline__ void epi_smem_h16(float c[4][4][4], unsigned* xbo,
                                             int l, int lane) {
    int g = lane >> 2, tg = lane & 3;
    __half* ob = (__half*)xbo;
    #pragma unroll
    for (int m = 0; m < 4; m++) {
        float b0 = g_bf[l*64 + m*16 + g];
        float b1 = g_bf[l*64 + m*16 + g + 8];
        #pragma unroll
        for (int nt = 0; nt < 4; nt++) {
            int px = nt*8 + 2*tg;
            ob[(px    )*(2*XW) + m*16 + g]     = __float2half_rn(fmaxf(c[m][nt][0] + b0, 0.f));
            ob[(px + 1)*(2*XW) + m*16 + g]     = __float2half_rn(fmaxf(c[m][nt][1] + b0, 0.f));
            ob[(px    )*(2*XW) + m*16 + g + 8] = __float2half_rn(fmaxf(c[m][nt][2] + b1, 0.f));
            ob[(px + 1)*(2*XW) + m*16 + g + 8] = __float2half_rn(fmaxf(c[m][nt][3] + b1, 0.f));
        }
    }
}

// bias + relu -> fp16 channel-last gmem (Q/K/V)
__device__ __forceinline__ void epi_gmem_h(float c[4][4][4], __half* base, int l, int lane, int px0) {
    int g = lane >> 2, tg = lane & 3;
    float bs0[4], bs1[4];
    #pragma unroll
    for (int m = 0; m < 4; m++) {
        bs0[m] = g_bf[l*64 + m*16 + g];
        bs1[m] = g_bf[l*64 + m*16 + g + 8];
    }
    #pragma unroll
    for (int nt = 0; nt < 4; nt++) {
        #pragma unroll
        for (int j = 0; j < 2; j++) {
            int px = px0 + nt*8 + 2*tg + j;
            int h = px / W_;
            int w = px - h*W_;
            __half* p = base + ((size_t)h*WP_ + w)*64;
            #pragma unroll
            for (int m = 0; m < 4; m++) {
                p[m*16 + g]     = __float2half_rn(fmaxf(c[m][nt][j]     + bs0[m], 0.f));
                p[m*16 + g + 8] = __float2half_rn(fmaxf(c[m][nt][2 + j] + bs1[m], 0.f));
            }
        }
    }
}

__global__ __launch_bounds__(128) void qkv_kernel(const float* __restrict__ img,
                                                  const float* __restrict__ wimg)
{
    extern __shared__ unsigned xs_u[];
    const int tid = threadIdx.x;
    const int wid = tid >> 5;
    const int lane = tid & 31;
    const int n = blockIdx.y;
    const int px0 = (blockIdx.x*4 + wid) * 32;

    unsigned* bufA = xs_u + wid * (2*XBUF_U);
    unsigned* bufB = bufA + XBUF_U;
    float c[4][4][4];

    const float* wsrc = wimg + (size_t)n*C_*HW_ + px0;
    const float* isrc = img  + (size_t)n*C_*HW_ + px0;
    __half* qb = (__half*)g_qh  + (size_t)n*H_*QW_*64;
    __half* kb = (__half*)g_kph + (((size_t)n*HP_ + PAD_)*WP_ + PAD_)*64;
    __half* vb = (__half*)g_vph + (((size_t)n*HP_ + PAD_)*WP_ + PAD_)*64;

    stage_tile_h(wsrc, bufA, lane);   __syncwarp();
    layer_mma_h(bufA, 4, lane, c);    epi_gmem_h(c, vb, 4, lane, px0);
    layer_mma_h(bufA, 2, lane, c);    epi_smem_h16(c, bufB, 2, lane);  __syncwarp();
    layer_mma_h(bufB, 3, lane, c);    epi_gmem_h(c, kb, 3, lane, px0);
    stage_tile_h(isrc, bufA, lane);   __syncwarp();
    layer_mma_h(bufA, 0, lane, c);    epi_smem_h16(c, bufB, 0, lane);  __syncwarp();
    layer_mma_h(bufB, 1, lane, c);    epi_gmem_h(c, qb, 1, lane, px0);
}

// ---------------- attention: fp16 K/V tiles, single-pass both phases ---------
// (byte-identical to round-13 proven version)
#define TR_   16
#define TC_   24
#define CPADH 36
#define KV2_F  (TR_*TC_*36)
#define SACC_F (8*16*84)
#define SMEM2_F (KV2_F + SACC_F + 8*16)
#define SMEM2_BYTES (SMEM2_F*4)

__device__ __forceinline__ void band_store(float* sa, float v, int px, int col, int di) {
    int dj = col - px;
    if ((unsigned)dj <= 8u)
        sa[px*84 + di*9 + dj] = v;
}

__global__ __launch_bounds__(256, 2) void attn_kernel(float* __restrict__ out)
{
    extern __shared__ float smem[];
    unsigned* kvu = (unsigned*)smem;
    float* sacc = smem + KV2_F;
    float* sinv = sacc + SACC_F;

    const int tid  = threadIdx.x;
    const int wid  = tid >> 5;
    const int lane = tid & 31;
    const int g    = lane >> 2;
    const int tg   = lane & 3;
    const int n  = blockIdx.z;
    const int h0 = blockIdx.y * 8;
    const int w0 = blockIdx.x * 16;
    const int h  = h0 + wid;

    {
        const uint4* kb = (const uint4*)(g_kph + (size_t)(n*HP_ + h0) * WP_ * 32);
        for (int i = tid; i < TR_*TC_*8; i += 256) {
            int px = i >> 3, c8 = i & 7;
            int r = px / TC_, c = px - r*TC_;
            int pcol = w0 + c; if (pcol > 207) pcol = 207;
            uint4 v = kb[((size_t)r*WP_ + pcol)*8 + c8];
            *(uint4*)(kvu + px*CPADH + c8*4) = v;
        }
    }

    unsigned qa[4][4];
    {
        const unsigned* q0 = g_qh + ((size_t)(n*H_ + h)*QW_ + (w0 + g))     * 32;
        const unsigned* q1 = g_qh + ((size_t)(n*H_ + h)*QW_ + (w0 + g + 8)) * 32;
        #pragma unroll
        for (int ks = 0; ks < 4; ks++) {
            qa[ks][0] = q0[ks*8 + tg];
            qa[ks][1] = q1[ks*8 + tg];
            qa[ks][2] = q0[ks*8 + tg + 4];
            qa[ks][3] = q1[ks*8 + tg + 4];
        }
    }
    __syncthreads();

    float* sa = sacc + wid*(16*84);

    #pragma unroll 1
    for (int di = 0; di < 9; di++) {
        float c0[3][4];
        #pragma unroll
        for (int nt = 0; nt < 3; nt++)
            #pragma unroll
            for (int j = 0; j < 4; j++) c0[nt][j] = 0.f;
        const unsigned* krow = kvu + (wid + di)*(TC_*CPADH);
        #pragma unroll
        for (int nt = 0; nt < 3; nt++) {
            const unsigned* kc = krow + (nt*8 + g)*CPADH;
            #pragma unroll
            for (int ks = 0; ks < 4; ks++) {
                unsigned b0 = kc[ks*8 + tg];
                unsigned b1 = kc[ks*8 + tg + 4];
                mma_f16(c0[nt], qa[ks], b0, b1);
            }
        }
        #pragma unroll
        for (int nt = 0; nt < 3; nt++) {
            int colb = nt*8 + 2*tg;
            band_store(sa, c0[nt][0], g,     colb,     di);
            band_store(sa, c0[nt][1], g,     colb + 1, di);
            band_store(sa, c0[nt][2], g + 8, colb,     di);
            band_store(sa, c0[nt][3], g + 8, colb + 1, di);
        }
    }
    __syncwarp();

    {
        int px   = lane & 15;
        int half = lane >> 4;
        float* sp = sa + px*84;
        int t0 = half * 41;
        int tc = 41 - half;
        float mx = -1e30f;
        for (int t = 0; t < tc; t++) {
            float v = sp[t0 + t] * 0.125f;
            mx = fmaxf(mx, v);
        }
        mx = fmaxf(mx, __shfl_xor_sync(0xffffffffu, mx, 16));
        float sum = 0.f;
        for (int t = 0; t < tc; t++) {
            float e = __expf(sp[t0 + t] * 0.125f - mx);
            sum += e;
            sp[t0 + t] = tf32r(e);
        }
        sum += __shfl_xor_sync(0xffffffffu, sum, 16);
        if (half == 0) sinv[wid*16 + px] = 1.f / sum;
    }
    __syncthreads();

    {
        const uint4* vb = (const uint4*)(g_vph + (size_t)(n*HP_ + h0) * WP_ * 32);
        for (int i = tid; i < TR_*TC_*8; i += 256) {
            int px = i >> 3, c8 = i & 7;
            int r = px / TC_, c = px - r*TC_;
            int pcol = w0 + c; if (pcol > 207) pcol = 207;
            uint4 v = vb[((size_t)r*WP_ + pcol)*8 + c8];
            *(uint4*)(kvu + px*CPADH + c8*4) = v;
        }
    }
    __syncthreads();

    float oc[4][2][4];
    #pragma unroll
    for (int mt = 0; mt < 4; mt++)
        #pragma unroll
        for (int nt = 0; nt < 2; nt++)
            #pragma unroll
            for (int j = 0; j < 4; j++) oc[mt][nt][j] = 0.f;

    #pragma unroll 1
    for (int di = 0; di < 9; di++) {
        const __half* vrow = (const __half*)(kvu + (wid + di)*(TC_*CPADH));
        #pragma unroll
        for (int kst = 0; kst < 3; kst++) {
            float bb[2][2];
            #pragma unroll
            for (int nt = 0; nt < 2; nt++) {
                int i0 = nt*8 + g;
                int j0 = kst*8 + tg;
                int dj0 = j0 - i0;
                int dj1 = dj0 + 4;
                bb[nt][0] = ((unsigned)dj0 <= 8u) ? sa[i0*84 + di*9 + dj0] : 0.f;
                bb[nt][1] = ((unsigned)dj1 <= 8u) ? sa[i0*84 + di*9 + dj1] : 0.f;
            }
            const __half* r0 = vrow + (kst*8 + tg)*72;
            const __half* r1 = vrow + (kst*8 + tg + 4)*72;
            #pragma unroll
            for (int mt = 0; mt < 4; mt++) {
                float av[4];
                av[0] = __half2float(r0[mt*16 + g]);
                av[1] = __half2float(r0[mt*16 + g + 8]);
                av[2] = __half2float(r1[mt*16 + g]);
                av[3] = __half2float(r1[mt*16 + g + 8]);
                mma_tf32(oc[mt][0], av, bb[0][0], bb[0][1]);
                mma_tf32(oc[mt][1], av, bb[1][0], bb[1][1]);
            }
        }
    }

    #pragma unroll
    for (int nt = 0; nt < 2; nt++) {
        int pxl = nt*8 + 2*tg;
        float is0 = sinv[wid*16 + pxl];
        float is1 = sinv[wid*16 + pxl + 1];
        int w = w0 + pxl;
        #pragma unroll
        for (int mt = 0; mt < 4; mt++) {
            int c  = mt*16 + g;
            float* ob0 = out + ((size_t)(n*C_ + c)*H_ + h)*W_;
            float* ob1 = out + ((size_t)(n*C_ + c + 8)*H_ + h)*W_;
            if (w < W_) {
                ob0[w] = oc[mt][nt][0] * is0;
                ob1[w] = oc[mt][nt][2] * is0;
            }
            if (w + 1 < W_) {
                ob0[w+1] = oc[mt][nt][1] * is1;
                ob1[w+1] = oc[mt][nt][3] * is1;
            }
        }
    }
}

// ---------------- launch ------------------------------------------------------
extern "C" void kernel_launch(void* const* d_in, const int* in_sizes, int n_in,
                              void* d_out, int out_size)
{
    (void)in_sizes; (void)n_in; (void)out_size;
    const float* img  = (const float*)d_in[0];
    const float* wimg = (const float*)d_in[1];
    const float* wc   = (const float*)d_in[2];
    const float* gg   = (const float*)d_in[3];
    const float* bb   = (const float*)d_in[4];
    const float* mm   = (const float*)d_in[5];
    const float* vv   = (const float*)d_in[6];
    float* out = (float*)d_out;

    static int attr_set = 0;
    if (!attr_set) {
        cudaFuncSetAttribute(attn_kernel,
                             cudaFuncAttributeMaxDynamicSharedMemorySize, SMEM2_BYTES);
        cudaFuncSetAttribute(qkv_kernel,
                             cudaFuncAttributeMaxDynamicSharedMemorySize, QKV_SMEM);
        attr_set = 1;
    }

    prep_kernel<<<(PREP_N + 255)/256, 256>>>(wc, gg, bb, mm, vv);

    dim3 qgrid(HW_/128, BN_);   // 175 x 6
    qkv_kernel<<<qgrid, 128, QKV_SMEM>>>(img, wimg);

    dim3 agrid((W_ + 15)/16, H_/8, BN_);   // 13 x 14 x 6
    attn_kernel<<<agrid, 256, SMEM2_BYTES>>>(out);
}

// round 15
// speedup vs baseline: 1.9654x; 1.0505x over previous
#include <cuda_runtime.h>
#include <cuda_fp16.h>
#include <math.h>

// Problem constants
#define H_    112
#define W_    200
#define HW_   (H_*W_)        // 22400
#define C_    64
#define BN_   6
#define PAD_  4
#define HP_   (H_ + 2*PAD_)  // 120
#define WP_   (W_ + 2*PAD_)  // 208
#define HPWP_ (HP_*WP_)      // 24960
#define QW_   208
#define NTAP  81

// fp16 mma, fp32 accumulate
__device__ __forceinline__ void mma_f16(float c[4], const unsigned a[4],
                                        unsigned b0, unsigned b1) {
    asm("mma.sync.aligned.m16n8k16.row.col.f32.f16.f16.f32 "
        "{%0,%1,%2,%3}, {%4,%5,%6,%7}, {%8,%9}, {%0,%1,%2,%3};"
        : "+f"(c[0]), "+f"(c[1]), "+f"(c[2]), "+f"(c[3])
        : "r"(a[0]), "r"(a[1]), "r"(a[2]), "r"(a[3]), "r"(b0), "r"(b1));
}

// ldmatrix x4 transposed b16 (loads 16x16 half tile transposed)
__device__ __forceinline__ void ldsm_x4_trans(unsigned r[4], unsigned saddr) {
    asm volatile("ldmatrix.sync.aligned.m8n8.x4.trans.shared.b16 {%0,%1,%2,%3}, [%4];"
        : "=r"(r[0]), "=r"(r[1]), "=r"(r[2]), "=r"(r[3]) : "r"(saddr));
}

__device__ __forceinline__ unsigned pack2h(float lo, float hi) {
    __half2 h = __floats2half2_rn(lo, hi);   // .x = lo -> low 16 bits
    return *reinterpret_cast<unsigned*>(&h);
}

// ---------------- scratch -----------------------------------------------------
__device__ unsigned g_qh  [BN_*H_*QW_*32];   // Q fp16, [n][h][w208][ch] (u32 = 2ch)
__device__ unsigned g_kph [BN_*HPWP_*32];    // K fp16, padded channel-last
__device__ unsigned g_vph [BN_*HPWP_*32];    // V fp16, padded channel-last
__device__ uint4    g_Whf [5*4*4*32];        // fp16 weight A-frags: [l][ks][m][lane]
__device__ float    g_bf  [5*64];            // folded bias

// ---------------- prep: fine-grained, one store per thread --------------------
#define PREP_W0   10240
#define PREP_B0   10560
#define PREP_K0   133440
#define PREP_V0   256320
#define PREP_N    299328

__device__ __forceinline__ void border_px(int j, int& row, int& col) {
    if (j < 1664) {
        int r = j / 208;
        col = j - r * 208;
        row = (r < 4) ? r : (112 + r);
    } else {
        int k = j - 1664;
        row = 4 + (k >> 3);
        int c = k & 7;
        col = (c < 4) ? c : (200 + c);
    }
}

__global__ void prep_kernel(const float* __restrict__ wc, const float* __restrict__ gam,
                            const float* __restrict__ bet, const float* __restrict__ mu,
                            const float* __restrict__ var) {
    int idx = blockIdx.x * 256 + threadIdx.x;
    if (idx < PREP_W0) {
        int l    = idx >> 11;
        int r    = idx & 2047;
        int ks   = r >> 9;
        int m    = (r >> 7) & 3;
        int lane = (r >> 2) & 31;
        int j    = r & 3;
        int g  = lane >> 2;
        int tg = lane & 3;
        int o  = m*16 + g + ((j & 1) ? 8 : 0);
        int k0 = ks*16 + 2*tg + ((j >= 2) ? 8 : 0);
        float s = gam[l*64 + o] * rsqrtf(var[l*64 + o] + 1e-5f);
        float w0 = s * wc[(l*64 + o)*64 + k0];
        float w1 = s * wc[(l*64 + o)*64 + k0 + 1];
        ((unsigned*)g_Whf)[idx] = pack2h(w0, w1);
    } else if (idx < PREP_B0) {
        int i = idx - PREP_W0;
        float s = gam[i] * rsqrtf(var[i] + 1e-5f);
        g_bf[i] = bet[i] - s * mu[i];
    } else if (idx < PREP_K0) {
        int it = idx - PREP_B0;
        int pxi = it >> 3, c8 = it & 7;
        int n = pxi / 2560, j = pxi - n*2560;
        int row, col; border_px(j, row, col);
        size_t px = (size_t)(n * HP_ + row) * WP_ + col;
        ((uint4*)(g_kph + px*32))[c8] = make_uint4(0, 0, 0, 0);
    } else if (idx < PREP_V0) {
        int it = idx - PREP_K0;
        int pxi = it >> 3, c8 = it & 7;
        int n = pxi / 2560, j = pxi - n*2560;
        int row, col; border_px(j, row, col);
        size_t px = (size_t)(n * HP_ + row) * WP_ + col;
        ((uint4*)(g_vph + px*32))[c8] = make_uint4(0, 0, 0, 0);
    } else if (idx < PREP_N) {
        int it = idx - PREP_V0;
        int pxi = it >> 3, c8 = it & 7;
        int n = pxi / (H_*8);
        int rr = pxi - n*(H_*8);
        int h = rr >> 3;
        int c = rr & 7;
        size_t px = (size_t)(n*H_ + h)*QW_ + 200 + c;
        ((uint4*)(g_qh + px*32))[c8] = make_uint4(0, 0, 0, 0);
    }
}

// ---------------- fused 5-layer QKV, full fp16 tensor cores (proven R14) -----
#define XW     36
#define XBUF_U (32*XW)
#define QKV_SMEM (4*2*XBUF_U*4)

__device__ __forceinline__ void stage_tile_h(const float* __restrict__ src,
                                             unsigned* xb, int lane) {
    int q = lane >> 3;
    int p = lane & 7;
    #pragma unroll
    for (int it = 0; it < 8; it++) {
        int cp = it*4 + q;
        float4 a = *(const float4*)(src + (size_t)(2*cp)    *HW_ + p*4);
        float4 b = *(const float4*)(src + (size_t)(2*cp + 1)*HW_ + p*4);
        xb[(p*4 + 0)*XW + cp] = pack2h(a.x, b.x);
        xb[(p*4 + 1)*XW + cp] = pack2h(a.y, b.y);
        xb[(p*4 + 2)*XW + cp] = pack2h(a.z, b.z);
        xb[(p*4 + 3)*XW + cp] = pack2h(a.w, b.w);
    }
}

__device__ __forceinline__ void layer_mma_h(const unsigned* xb, int l, int lane,
                                            float c[4][4][4]) {
    int g = lane >> 2, tg = lane & 3;
    #pragma unroll
    for (int m = 0; m < 4; m++)
        #pragma unroll
        for (int nt = 0; nt < 4; nt++)
            #pragma unroll
            for (int j = 0; j < 4; j++) c[m][nt][j] = 0.f;

    const uint4* wf = g_Whf + (size_t)l*512;
    #pragma unroll
    for (int ks = 0; ks < 4; ks++) {
        uint4 a[4];
        #pragma unroll
        for (int m = 0; m < 4; m++)
            a[m] = __ldg(wf + (ks*4 + m)*32 + lane);
        #pragma unroll
        for (int nt = 0; nt < 4; nt++) {
            unsigned b0 = xb[(nt*8 + g)*XW + ks*8 + tg];
            unsigned b1 = xb[(nt*8 + g)*XW + ks*8 + tg + 4];
            #pragma unroll
            for (int m = 0; m < 4; m++)
                mma_f16(c[m][nt], (const unsigned*)&a[m], b0, b1);
        }
    }
}

__device__ __forceinline__ void epi_smem_h16(float c[4][4][4], unsigned* xbo,
                                             int l, int lane) {
    int g = lane >> 2, tg = lane & 3;
    __half* ob = (__half*)xbo;
    #pragma unroll
    for (int m = 0; m < 4; m++) {
        float b0 = g_bf[l*64 + m*16 + g];
        float b1 = g_bf[l*64 + m*16 + g + 8];
        #pragma unroll
        for (int nt = 0; nt < 4; nt++) {
            int px = nt*8 + 2*tg;
            ob[(px    )*(2*XW) + m*16 + g]     = __float2half_rn(fmaxf(c[m][nt][0] + b0, 0.f));
            ob[(px + 1)*(2*XW) + m*16 + g]     = __float2half_rn(fmaxf(c[m][nt][1] + b0, 0.f));
            ob[(px    )*(2*XW) + m*16 + g + 8] = __float2half_rn(fmaxf(c[m][nt][2] + b1, 0.f));
            ob[(px + 1)*(2*XW) + m*16 + g + 8] = __float2half_rn(fmaxf(c[m][nt][3] + b1, 0.f));
        }
    }
}

__device__ __forceinline__ void epi_gmem_h(float c[4][4][4], __half* base, int l, int lane, int px0) {
    int g = lane >> 2, tg = lane & 3;
    float bs0[4], bs1[4];
    #pragma unroll
    for (int m = 0; m < 4; m++) {
        bs0[m] = g_bf[l*64 + m*16 + g];
        bs1[m] = g_bf[l*64 + m*16 + g + 8];
    }
    #pragma unroll
    for (int nt = 0; nt < 4; nt++) {
        #pragma unroll
        for (int j = 0; j < 2; j++) {
            int px = px0 + nt*8 + 2*tg + j;
            int h = px / W_;
            int w = px - h*W_;
            __half* p = base + ((size_t)h*WP_ + w)*64;
            #pragma unroll
            for (int m = 0; m < 4; m++) {
                p[m*16 + g]     = __float2half_rn(fmaxf(c[m][nt][j]     + bs0[m], 0.f));
                p[m*16 + g + 8] = __float2half_rn(fmaxf(c[m][nt][2 + j] + bs1[m], 0.f));
            }
        }
    }
}

__global__ __launch_bounds__(128) void qkv_kernel(const float* __restrict__ img,
                                                  const float* __restrict__ wimg)
{
    extern __shared__ unsigned xs_u[];
    const int tid = threadIdx.x;
    const int wid = tid >> 5;
    const int lane = tid & 31;
    const int n = blockIdx.y;
    const int px0 = (blockIdx.x*4 + wid) * 32;

    unsigned* bufA = xs_u + wid * (2*XBUF_U);
    unsigned* bufB = bufA + XBUF_U;
    float c[4][4][4];

    const float* wsrc = wimg + (size_t)n*C_*HW_ + px0;
    const float* isrc = img  + (size_t)n*C_*HW_ + px0;
    __half* qb = (__half*)g_qh  + (size_t)n*H_*QW_*64;
    __half* kb = (__half*)g_kph + (((size_t)n*HP_ + PAD_)*WP_ + PAD_)*64;
    __half* vb = (__half*)g_vph + (((size_t)n*HP_ + PAD_)*WP_ + PAD_)*64;

    stage_tile_h(wsrc, bufA, lane);   __syncwarp();
    layer_mma_h(bufA, 4, lane, c);    epi_gmem_h(c, vb, 4, lane, px0);
    layer_mma_h(bufA, 2, lane, c);    epi_smem_h16(c, bufB, 2, lane);  __syncwarp();
    layer_mma_h(bufB, 3, lane, c);    epi_gmem_h(c, kb, 3, lane, px0);
    stage_tile_h(isrc, bufA, lane);   __syncwarp();
    layer_mma_h(bufA, 0, lane, c);    epi_smem_h16(c, bufB, 0, lane);  __syncwarp();
    layer_mma_h(bufB, 1, lane, c);    epi_gmem_h(c, qb, 1, lane, px0);
}

// ---------------- attention: full fp16, ldmatrix V^T phase 2 -----------------
#define TR_   16
#define TC_   24
#define CPADH 36
#define KV2_F  (TR_*TC_*36)
#define SACC_F (8*16*84)
#define SMEM2_F (KV2_F + SACC_F + 8*16)
#define SMEM2_BYTES (SMEM2_F*4)

__device__ __forceinline__ void band_store(float* sa, float v, int px, int col, int di) {
    int dj = col - px;
    if ((unsigned)dj <= 8u)
        sa[px*84 + di*9 + dj] = v;
}

__global__ __launch_bounds__(256, 2) void attn_kernel(float* __restrict__ out)
{
    extern __shared__ float smem[];
    unsigned* kvu = (unsigned*)smem;
    float* sacc = smem + KV2_F;
    float* sinv = sacc + SACC_F;

    const int tid  = threadIdx.x;
    const int wid  = tid >> 5;
    const int lane = tid & 31;
    const int g    = lane >> 2;
    const int tg   = lane & 3;
    const int n  = blockIdx.z;
    const int h0 = blockIdx.y * 8;
    const int w0 = blockIdx.x * 16;
    const int h  = h0 + wid;

    // ---- stage full 64-ch fp16 K tile ----
    {
        const uint4* kb = (const uint4*)(g_kph + (size_t)(n*HP_ + h0) * WP_ * 32);
        for (int i = tid; i < TR_*TC_*8; i += 256) {
            int px = i >> 3, c8 = i & 7;
            int r = px / TC_, c = px - r*TC_;
            int pcol = w0 + c; if (pcol > 207) pcol = 207;
            uint4 v = kb[((size_t)r*WP_ + pcol)*8 + c8];
            *(uint4*)(kvu + px*CPADH + c8*4) = v;
        }
    }

    // ---- Q fp16 A-fragments ----
    unsigned qa[4][4];
    {
        const unsigned* q0 = g_qh + ((size_t)(n*H_ + h)*QW_ + (w0 + g))     * 32;
        const unsigned* q1 = g_qh + ((size_t)(n*H_ + h)*QW_ + (w0 + g + 8)) * 32;
        #pragma unroll
        for (int ks = 0; ks < 4; ks++) {
            qa[ks][0] = q0[ks*8 + tg];
            qa[ks][1] = q1[ks*8 + tg];
            qa[ks][2] = q0[ks*8 + tg + 4];
            qa[ks][3] = q1[ks*8 + tg + 4];
        }
    }
    __syncthreads();

    float* sa = sacc + wid*(16*84);

    // ---- phase 1: similarity, fp16 mma, direct band store ----
    #pragma unroll 1
    for (int di = 0; di < 9; di++) {
        float c0[3][4];
        #pragma unroll
        for (int nt = 0; nt < 3; nt++)
            #pragma unroll
            for (int j = 0; j < 4; j++) c0[nt][j] = 0.f;
        const unsigned* krow = kvu + (wid + di)*(TC_*CPADH);
        #pragma unroll
        for (int nt = 0; nt < 3; nt++) {
            const unsigned* kc = krow + (nt*8 + g)*CPADH;
            #pragma unroll
            for (int ks = 0; ks < 4; ks++) {
                unsigned b0 = kc[ks*8 + tg];
                unsigned b1 = kc[ks*8 + tg + 4];
                mma_f16(c0[nt], qa[ks], b0, b1);
            }
        }
        #pragma unroll
        for (int nt = 0; nt < 3; nt++) {
            int colb = nt*8 + 2*tg;
            band_store(sa, c0[nt][0], g,     colb,     di);
            band_store(sa, c0[nt][1], g,     colb + 1, di);
            band_store(sa, c0[nt][2], g + 8, colb,     di);
            band_store(sa, c0[nt][3], g + 8, colb + 1, di);
        }
    }
    __syncwarp();

    // ---- softmax (2 lanes per px) ----
    {
        int px   = lane & 15;
        int half = lane >> 4;
        float* sp = sa + px*84;
        int t0 = half * 41;
        int tc = 41 - half;
        float mx = -1e30f;
        for (int t = 0; t < tc; t++) {
            float v = sp[t0 + t] * 0.125f;
            mx = fmaxf(mx, v);
        }
        mx = fmaxf(mx, __shfl_xor_sync(0xffffffffu, mx, 16));
        float sum = 0.f;
        for (int t = 0; t < tc; t++) {
            float e = __expf(sp[t0 + t] * 0.125f - mx);
            sum += e;
            sp[t0 + t] = e;
        }
        sum += __shfl_xor_sync(0xffffffffu, sum, 16);
        if (half == 0) sinv[wid*16 + px] = 1.f / sum;
    }
    __syncthreads();   // all warps done with K tile + softmax before V overwrite

    // ---- stage full 64-ch fp16 V tile ----
    {
        const uint4* vb = (const uint4*)(g_vph + (size_t)(n*HP_ + h0) * WP_ * 32);
        for (int i = tid; i < TR_*TC_*8; i += 256) {
            int px = i >> 3, c8 = i & 7;
            int r = px / TC_, c = px - r*TC_;
            int pcol = w0 + c; if (pcol > 207) pcol = 207;
            uint4 v = vb[((size_t)r*WP_ + pcol)*8 + c8];
            *(uint4*)(kvu + px*CPADH + c8*4) = v;
        }
    }
    __syncthreads();

    // ---- phase 2: fp16 mma, V^T via ldmatrix.x4.trans ----
    // D[16 ch][8 px] per mma; K = 16 w' = exact 8px+8tap window per px-group.
    float oc[4][2][4];
    #pragma unroll
    for (int mt = 0; mt < 4; mt++)
        #pragma unroll
        for (int pxg = 0; pxg < 2; pxg++)
            #pragma unroll
            for (int j = 0; j < 4; j++) oc[mt][pxg][j] = 0.f;

    const unsigned kv_sbase = (unsigned)__cvta_generic_to_shared(kvu);
    const int wl     = (lane & 7) + ((lane >> 4) << 3);   // w' row 0..15
    const int ch_off = ((lane >> 3) & 1) * 8;             // +0 or +8 halves

    #pragma unroll 1
    for (int di = 0; di < 9; di++) {
        #pragma unroll
        for (int pxg = 0; pxg < 2; pxg++) {
            // B = softmax weights: b0 = P(k=2tg,2tg+1), b1 = P(k=2tg+8,+9), n = px g
            int dj0 = 2*tg - g;
            const float* sb = sa + (pxg*8 + g)*84 + di*9;
            float p0 = ((unsigned)(dj0)     <= 8u) ? sb[dj0]     : 0.f;
            float p1 = ((unsigned)(dj0 + 1) <= 8u) ? sb[dj0 + 1] : 0.f;
            float p2 = ((unsigned)(dj0 + 8) <= 8u) ? sb[dj0 + 8] : 0.f;
            float p3 = ((unsigned)(dj0 + 9) <= 8u) ? sb[dj0 + 9] : 0.f;
            unsigned b0 = pack2h(p0, p1);
            unsigned b1 = pack2h(p2, p3);

            // A = V^T[ch][w'] via ldmatrix.trans on rows of V (w' rows, 16B of ch)
            unsigned rowaddr = kv_sbase +
                ((((wid + di)*TC_ + pxg*8 + wl) * 72) + ch_off) * 2;
            #pragma unroll
            for (int mt = 0; mt < 4; mt++) {
                unsigned a[4];
                ldsm_x4_trans(a, rowaddr + mt*32);
                mma_f16(oc[mt][pxg], a, b0, b1);
            }
        }
    }

    // ---- epilogue: scale by 1/sum, store NCHW ----
    #pragma unroll
    for (int pxg = 0; pxg < 2; pxg++) {
        int pxl = pxg*8 + 2*tg;
        float is0 = sinv[wid*16 + pxl];
        float is1 = sinv[wid*16 + pxl + 1];
        int w = w0 + pxl;
        #pragma unroll
        for (int mt = 0; mt < 4; mt++) {
            int c  = mt*16 + g;
            float* ob0 = out + ((size_t)(n*C_ + c)*H_ + h)*W_;
            float* ob1 = out + ((size_t)(n*C_ + c + 8)*H_ + h)*W_;
            if (w < W_) {
                ob0[w] = oc[mt][pxg][0] * is0;
                ob1[w] = oc[mt][pxg][2] * is0;
            }
            if (w + 1 < W_) {
                ob0[w+1] = oc[mt][pxg][1] * is1;
                ob1[w+1] = oc[mt][pxg][3] * is1;
            }
        }
    }
}

// ---------------- launch ------------------------------------------------------
extern "C" void kernel_launch(void* const* d_in, const int* in_sizes, int n_in,
                              void* d_out, int out_size)
{
    (void)in_sizes; (void)n_in; (void)out_size;
    const float* img  = (const float*)d_in[0];
    const float* wimg = (const float*)d_in[1];
    const float* wc   = (const float*)d_in[2];
    const float* gg   = (const float*)d_in[3];
    const float* bb   = (const float*)d_in[4];
    const float* mm   = (const float*)d_in[5];
    const float* vv   = (const float*)d_in[6];
    float* out = (float*)d_out;

    static int attr_set = 0;
    if (!attr_set) {
        cudaFuncSetAttribute(attn_kernel,
                             cudaFuncAttributeMaxDynamicSharedMemorySize, SMEM2_BYTES);
        cudaFuncSetAttribute(qkv_kernel,
                             cudaFuncAttributeMaxDynamicSharedMemorySize, QKV_SMEM);
        attr_set = 1;
    }

    prep_kernel<<<(PREP_N + 255)/256, 256>>>(wc, gg, bb, mm, vv);

    dim3 qgrid(HW_/128, BN_);   // 175 x 6
    qkv_kernel<<<qgrid, 128, QKV_SMEM>>>(img, wimg);

    dim3 agrid((W_ + 15)/16, H_/8, BN_);   // 13 x 14 x 6
    attn_kernel<<<agrid, 256, SMEM2_BYTES>>>(out);
}

// round 16
// speedup vs baseline: 2.2708x; 1.1553x over previous
#include <cuda_runtime.h>
#include <cuda_fp16.h>
#include <math.h>

// Problem constants
#define H_    112
#define W_    200
#define HW_   (H_*W_)        // 22400
#define C_    64
#define BN_   6
#define PAD_  4
#define HP_   (H_ + 2*PAD_)  // 120
#define WP_   (W_ + 2*PAD_)  // 208
#define HPWP_ (HP_*WP_)      // 24960
#define QW_   208
#define NTAP  81

// fp16 mma, fp32 accumulate
__device__ __forceinline__ void mma_f16(float c[4], const unsigned a[4],
                                        unsigned b0, unsigned b1) {
    asm("mma.sync.aligned.m16n8k16.row.col.f32.f16.f16.f32 "
        "{%0,%1,%2,%3}, {%4,%5,%6,%7}, {%8,%9}, {%0,%1,%2,%3};"
        : "+f"(c[0]), "+f"(c[1]), "+f"(c[2]), "+f"(c[3])
        : "r"(a[0]), "r"(a[1]), "r"(a[2]), "r"(a[3]), "r"(b0), "r"(b1));
}

// ldmatrix x4 transposed b16
__device__ __forceinline__ void ldsm_x4_trans(unsigned r[4], unsigned saddr) {
    asm volatile("ldmatrix.sync.aligned.m8n8.x4.trans.shared.b16 {%0,%1,%2,%3}, [%4];"
        : "=r"(r[0]), "=r"(r[1]), "=r"(r[2]), "=r"(r[3]) : "r"(saddr));
}

__device__ __forceinline__ unsigned pack2h(float lo, float hi) {
    __half2 h = __floats2half2_rn(lo, hi);
    return *reinterpret_cast<unsigned*>(&h);
}

// cp.async 16B (LDGSTS)
__device__ __forceinline__ void cp_async16(unsigned saddr, const void* gaddr) {
    asm volatile("cp.async.cg.shared.global [%0], [%1], 16;" :: "r"(saddr), "l"(gaddr));
}
#define CP_COMMIT() asm volatile("cp.async.commit_group;" ::: "memory")
#define CP_WAIT0()  asm volatile("cp.async.wait_group 0;" ::: "memory")

// ---------------- scratch -----------------------------------------------------
__device__ unsigned g_qh  [BN_*H_*QW_*32];   // Q fp16, [n][h][w208][ch] (u32 = 2ch)
__device__ unsigned g_kph [BN_*HPWP_*32];    // K fp16, padded channel-last
__device__ unsigned g_vph [BN_*HPWP_*32];    // V fp16, padded channel-last
__device__ uint4    g_Whf [5*4*4*32];        // fp16 weight A-frags: [l][ks][m][lane]
__device__ float    g_bf  [5*64];            // folded bias

// ---------------- prep: fine-grained, one store per thread --------------------
#define PREP_W0   10240
#define PREP_B0   10560
#define PREP_K0   133440
#define PREP_V0   256320
#define PREP_N    299328

__device__ __forceinline__ void border_px(int j, int& row, int& col) {
    if (j < 1664) {
        int r = j / 208;
        col = j - r * 208;
        row = (r < 4) ? r : (112 + r);
    } else {
        int k = j - 1664;
        row = 4 + (k >> 3);
        int c = k & 7;
        col = (c < 4) ? c : (200 + c);
    }
}

__global__ void prep_kernel(const float* __restrict__ wc, const float* __restrict__ gam,
                            const float* __restrict__ bet, const float* __restrict__ mu,
                            const float* __restrict__ var) {
    int idx = blockIdx.x * 256 + threadIdx.x;
    if (idx < PREP_W0) {
        int l    = idx >> 11;
        int r    = idx & 2047;
        int ks   = r >> 9;
        int m    = (r >> 7) & 3;
        int lane = (r >> 2) & 31;
        int j    = r & 3;
        int g  = lane >> 2;
        int tg = lane & 3;
        int o  = m*16 + g + ((j & 1) ? 8 : 0);
        int k0 = ks*16 + 2*tg + ((j >= 2) ? 8 : 0);
        float s = gam[l*64 + o] * rsqrtf(var[l*64 + o] + 1e-5f);
        float w0 = s * wc[(l*64 + o)*64 + k0];
        float w1 = s * wc[(l*64 + o)*64 + k0 + 1];
        ((unsigned*)g_Whf)[idx] = pack2h(w0, w1);
    } else if (idx < PREP_B0) {
        int i = idx - PREP_W0;
        float s = gam[i] * rsqrtf(var[i] + 1e-5f);
        g_bf[i] = bet[i] - s * mu[i];
    } else if (idx < PREP_K0) {
        int it = idx - PREP_B0;
        int pxi = it >> 3, c8 = it & 7;
        int n = pxi / 2560, j = pxi - n*2560;
        int row, col; border_px(j, row, col);
        size_t px = (size_t)(n * HP_ + row) * WP_ + col;
        ((uint4*)(g_kph + px*32))[c8] = make_uint4(0, 0, 0, 0);
    } else if (idx < PREP_V0) {
        int it = idx - PREP_K0;
        int pxi = it >> 3, c8 = it & 7;
        int n = pxi / 2560, j = pxi - n*2560;
        int row, col; border_px(j, row, col);
        size_t px = (size_t)(n * HP_ + row) * WP_ + col;
        ((uint4*)(g_vph + px*32))[c8] = make_uint4(0, 0, 0, 0);
    } else if (idx < PREP_N) {
        int it = idx - PREP_V0;
        int pxi = it >> 3, c8 = it & 7;
        int n = pxi / (H_*8);
        int rr = pxi - n*(H_*8);
        int h = rr >> 3;
        int c = rr & 7;
        size_t px = (size_t)(n*H_ + h)*QW_ + 200 + c;
        ((uint4*)(g_qh + px*32))[c8] = make_uint4(0, 0, 0, 0);
    }
}

// ---------------- fused 5-layer QKV, full fp16 tensor cores (proven R14) -----
#define XW     36
#define XBUF_U (32*XW)
#define QKV_SMEM (4*2*XBUF_U*4)

__device__ __forceinline__ void stage_tile_h(const float* __restrict__ src,
                                             unsigned* xb, int lane) {
    int q = lane >> 3;
    int p = lane & 7;
    #pragma unroll
    for (int it = 0; it < 8; it++) {
        int cp = it*4 + q;
        float4 a = *(const float4*)(src + (size_t)(2*cp)    *HW_ + p*4);
        float4 b = *(const float4*)(src + (size_t)(2*cp + 1)*HW_ + p*4);
        xb[(p*4 + 0)*XW + cp] = pack2h(a.x, b.x);
        xb[(p*4 + 1)*XW + cp] = pack2h(a.y, b.y);
        xb[(p*4 + 2)*XW + cp] = pack2h(a.z, b.z);
        xb[(p*4 + 3)*XW + cp] = pack2h(a.w, b.w);
    }
}

__device__ __forceinline__ void layer_mma_h(const unsigned* xb, int l, int lane,
                                            float c[4][4][4]) {
    int g = lane >> 2, tg = lane & 3;
    #pragma unroll
    for (int m = 0; m < 4; m++)
        #pragma unroll
        for (int nt = 0; nt < 4; nt++)
            #pragma unroll
            for (int j = 0; j < 4; j++) c[m][nt][j] = 0.f;

    const uint4* wf = g_Whf + (size_t)l*512;
    #pragma unroll
    for (int ks = 0; ks < 4; ks++) {
        uint4 a[4];
        #pragma unroll
        for (int m = 0; m < 4; m++)
            a[m] = __ldg(wf + (ks*4 + m)*32 + lane);
        #pragma unroll
        for (int nt = 0; nt < 4; nt++) {
            unsigned b0 = xb[(nt*8 + g)*XW + ks*8 + tg];
            unsigned b1 = xb[(nt*8 + g)*XW + ks*8 + tg + 4];
            #pragma unroll
            for (int m = 0; m < 4; m++)
                mma_f16(c[m][nt], (const unsigned*)&a[m], b0, b1);
        }
    }
}

__device__ __forceinline__ void epi_smem_h16(float c[4][4][4], unsigned* xbo,
                                             int l, int lane) {
    int g = lane >> 2, tg = lane & 3;
    __half* ob = (__half*)xbo;
    #pragma unroll
    for (int m = 0; m < 4; m++) {
        float b0 = g_bf[l*64 + m*16 + g];
        float b1 = g_bf[l*64 + m*16 + g + 8];
        #pragma unroll
        for (int nt = 0; nt < 4; nt++) {
            int px = nt*8 + 2*tg;
            ob[(px    )*(2*XW) + m*16 + g]     = __float2half_rn(fmaxf(c[m][nt][0] + b0, 0.f));
            ob[(px + 1)*(2*XW) + m*16 + g]     = __float2half_rn(fmaxf(c[m][nt][1] + b0, 0.f));
            ob[(px    )*(2*XW) + m*16 + g + 8] = __float2half_rn(fmaxf(c[m][nt][2] + b1, 0.f));
            ob[(px + 1)*(2*XW) + m*16 + g + 8] = __float2half_rn(fmaxf(c[m][nt][3] + b1, 0.f));
        }
    }
}

__device__ __forceinline__ void epi_gmem_h(float c[4][4][4], __half* base, int l, int lane, int px0) {
    int g = lane >> 2, tg = lane & 3;
    float bs0[4], bs1[4];
    #pragma unroll
    for (int m = 0; m < 4; m++) {
        bs0[m] = g_bf[l*64 + m*16 + g];
        bs1[m] = g_bf[l*64 + m*16 + g + 8];
    }
    #pragma unroll
    for (int nt = 0; nt < 4; nt++) {
        #pragma unroll
        for (int j = 0; j < 2; j++) {
            int px = px0 + nt*8 + 2*tg + j;
            int h = px / W_;
            int w = px - h*W_;
            __half* p = base + ((size_t)h*WP_ + w)*64;
            #pragma unroll
            for (int m = 0; m < 4; m++) {
                p[m*16 + g]     = __float2half_rn(fmaxf(c[m][nt][j]     + bs0[m], 0.f));
                p[m*16 + g + 8] = __float2half_rn(fmaxf(c[m][nt][2 + j] + bs1[m], 0.f));
            }
        }
    }
}

__global__ __launch_bounds__(128) void qkv_kernel(const float* __restrict__ img,
                                                  const float* __restrict__ wimg)
{
    extern __shared__ unsigned xs_u[];
    const int tid = threadIdx.x;
    const int wid = tid >> 5;
    const int lane = tid & 31;
    const int n = blockIdx.y;
    const int px0 = (blockIdx.x*4 + wid) * 32;

    unsigned* bufA = xs_u + wid * (2*XBUF_U);
    unsigned* bufB = bufA + XBUF_U;
    float c[4][4][4];

    const float* wsrc = wimg + (size_t)n*C_*HW_ + px0;
    const float* isrc = img  + (size_t)n*C_*HW_ + px0;
    __half* qb = (__half*)g_qh  + (size_t)n*H_*QW_*64;
    __half* kb = (__half*)g_kph + (((size_t)n*HP_ + PAD_)*WP_ + PAD_)*64;
    __half* vb = (__half*)g_vph + (((size_t)n*HP_ + PAD_)*WP_ + PAD_)*64;

    stage_tile_h(wsrc, bufA, lane);   __syncwarp();
    layer_mma_h(bufA, 4, lane, c);    epi_gmem_h(c, vb, 4, lane, px0);
    layer_mma_h(bufA, 2, lane, c);    epi_smem_h16(c, bufB, 2, lane);  __syncwarp();
    layer_mma_h(bufB, 3, lane, c);    epi_gmem_h(c, kb, 3, lane, px0);
    stage_tile_h(isrc, bufA, lane);   __syncwarp();
    layer_mma_h(bufA, 0, lane, c);    epi_smem_h16(c, bufB, 0, lane);  __syncwarp();
    layer_mma_h(bufB, 1, lane, c);    epi_gmem_h(c, qb, 1, lane, px0);
}

// ---------------- attention: full fp16, cp.async staged tiles ----------------
#define TR_   16
#define TC_   24
#define CPADH 36
#define KV2_F  (TR_*TC_*36)
#define SACC_F (8*16*84)
#define SMEM2_F (KV2_F + SACC_F + 8*16)
#define SMEM2_BYTES (SMEM2_F*4)

__device__ __forceinline__ void band_store(float* sa, float v, int px, int col, int di) {
    int dj = col - px;
    if ((unsigned)dj <= 8u)
        sa[px*84 + di*9 + dj] = v;
}

__global__ __launch_bounds__(256, 2) void attn_kernel(float* __restrict__ out)
{
    extern __shared__ float smem[];
    unsigned* kvu = (unsigned*)smem;
    float* sacc = smem + KV2_F;
    float* sinv = sacc + SACC_F;

    const int tid  = threadIdx.x;
    const int wid  = tid >> 5;
    const int lane = tid & 31;
    const int g    = lane >> 2;
    const int tg   = lane & 3;
    const int n  = blockIdx.z;
    const int h0 = blockIdx.y * 8;
    const int w0 = blockIdx.x * 16;
    const int h  = h0 + wid;

    const unsigned kv_sbase = (unsigned)__cvta_generic_to_shared(kvu);

    // ---- stage K tile via cp.async (latency hidden behind qa loads) ----
    {
        const uint4* kb = (const uint4*)(g_kph + (size_t)(n*HP_ + h0) * WP_ * 32);
        for (int i = tid; i < TR_*TC_*8; i += 256) {
            int px = i >> 3, c8 = i & 7;
            int r = px / TC_, c = px - r*TC_;
            int pcol = w0 + c; if (pcol > 207) pcol = 207;
            cp_async16(kv_sbase + (px*CPADH + c8*4)*4,
                       kb + ((size_t)r*WP_ + pcol)*8 + c8);
        }
        CP_COMMIT();
    }

    // ---- Q fp16 A-fragments (overlaps K cp.async) ----
    unsigned qa[4][4];
    {
        const unsigned* q0 = g_qh + ((size_t)(n*H_ + h)*QW_ + (w0 + g))     * 32;
        const unsigned* q1 = g_qh + ((size_t)(n*H_ + h)*QW_ + (w0 + g + 8)) * 32;
        #pragma unroll
        for (int ks = 0; ks < 4; ks++) {
            qa[ks][0] = q0[ks*8 + tg];
            qa[ks][1] = q1[ks*8 + tg];
            qa[ks][2] = q0[ks*8 + tg + 4];
            qa[ks][3] = q1[ks*8 + tg + 4];
        }
    }
    CP_WAIT0();
    __syncthreads();

    float* sa = sacc + wid*(16*84);

    // ---- phase 1: similarity, fp16 mma, direct band store ----
    #pragma unroll 1
    for (int di = 0; di < 9; di++) {
        float c0[3][4];
        #pragma unroll
        for (int nt = 0; nt < 3; nt++)
            #pragma unroll
            for (int j = 0; j < 4; j++) c0[nt][j] = 0.f;
        const unsigned* krow = kvu + (wid + di)*(TC_*CPADH);
        #pragma unroll
        for (int nt = 0; nt < 3; nt++) {
            const unsigned* kc = krow + (nt*8 + g)*CPADH;
            #pragma unroll
            for (int ks = 0; ks < 4; ks++) {
                unsigned b0 = kc[ks*8 + tg];
                unsigned b1 = kc[ks*8 + tg + 4];
                mma_f16(c0[nt], qa[ks], b0, b1);
            }
        }
        #pragma unroll
        for (int nt = 0; nt < 3; nt++) {
            int colb = nt*8 + 2*tg;
            band_store(sa, c0[nt][0], g,     colb,     di);
            band_store(sa, c0[nt][1], g,     colb + 1, di);
            band_store(sa, c0[nt][2], g + 8, colb,     di);
            band_store(sa, c0[nt][3], g + 8, colb + 1, di);
        }
    }
    __syncthreads();   // all warps done reading K tile (and band visible warp-locally)

    // ---- issue V tile cp.async NOW; softmax hides the fetch latency ----
    {
        const uint4* vb = (const uint4*)(g_vph + (size_t)(n*HP_ + h0) * WP_ * 32);
        for (int i = tid; i < TR_*TC_*8; i += 256) {
            int px = i >> 3, c8 = i & 7;
            int r = px / TC_, c = px - r*TC_;
            int pcol = w0 + c; if (pcol > 207) pcol = 207;
            cp_async16(kv_sbase + (px*CPADH + c8*4)*4,
                       vb + ((size_t)r*WP_ + pcol)*8 + c8);
        }
        CP_COMMIT();
    }

    // ---- softmax (2 lanes per px) — reads/writes sacc only ----
    {
        int px   = lane & 15;
        int half = lane >> 4;
        float* sp = sa + px*84;
        int t0 = half * 41;
        int tc = 41 - half;
        float mx = -1e30f;
        for (int t = 0; t < tc; t++) {
            float v = sp[t0 + t] * 0.125f;
            mx = fmaxf(mx, v);
        }
        mx = fmaxf(mx, __shfl_xor_sync(0xffffffffu, mx, 16));
        float sum = 0.f;
        for (int t = 0; t < tc; t++) {
            float e = __expf(sp[t0 + t] * 0.125f - mx);
            sum += e;
            sp[t0 + t] = e;
        }
        sum += __shfl_xor_sync(0xffffffffu, sum, 16);
        if (half == 0) sinv[wid*16 + px] = 1.f / sum;
    }

    CP_WAIT0();
    __syncthreads();

    // ---- phase 2: fp16 mma, V^T via ldmatrix.x4.trans ----
    float oc[4][2][4];
    #pragma unroll
    for (int mt = 0; mt < 4; mt++)
        #pragma unroll
        for (int pxg = 0; pxg < 2; pxg++)
            #pragma unroll
            for (int j = 0; j < 4; j++) oc[mt][pxg][j] = 0.f;

    const int wl     = (lane & 7) + ((lane >> 4) << 3);   // w' row 0..15
    const int ch_off = ((lane >> 3) & 1) * 8;             // +0 or +8 halves

    #pragma unroll 1
    for (int di = 0; di < 9; di++) {
        #pragma unroll
        for (int pxg = 0; pxg < 2; pxg++) {
            int dj0 = 2*tg - g;
            const float* sb = sa + (pxg*8 + g)*84 + di*9;
            float p0 = ((unsigned)(dj0)     <= 8u) ? sb[dj0]     : 0.f;
            float p1 = ((unsigned)(dj0 + 1) <= 8u) ? sb[dj0 + 1] : 0.f;
            float p2 = ((unsigned)(dj0 + 8) <= 8u) ? sb[dj0 + 8] : 0.f;
            float p3 = ((unsigned)(dj0 + 9) <= 8u) ? sb[dj0 + 9] : 0.f;
            unsigned b0 = pack2h(p0, p1);
            unsigned b1 = pack2h(p2, p3);

            unsigned rowaddr = kv_sbase +
                ((((wid + di)*TC_ + pxg*8 + wl) * 72) + ch_off) * 2;
            #pragma unroll
            for (int mt = 0; mt < 4; mt++) {
                unsigned a[4];
                ldsm_x4_trans(a, rowaddr + mt*32);
                mma_f16(oc[mt][pxg], a, b0, b1);
            }
        }
    }

    // ---- epilogue: scale by 1/sum, store NCHW ----
    #pragma unroll
    for (int pxg = 0; pxg < 2; pxg++) {
        int pxl = pxg*8 + 2*tg;
        float is0 = sinv[wid*16 + pxl];
        float is1 = sinv[wid*16 + pxl + 1];
        int w = w0 + pxl;
        #pragma unroll
        for (int mt = 0; mt < 4; mt++) {
            int c  = mt*16 + g;
            float* ob0 = out + ((size_t)(n*C_ + c)*H_ + h)*W_;
            float* ob1 = out + ((size_t)(n*C_ + c + 8)*H_ + h)*W_;
            if (w < W_) {
                ob0[w] = oc[mt][pxg][0] * is0;
                ob1[w] = oc[mt][pxg][2] * is0;
            }
            if (w + 1 < W_) {
                ob0[w+1] = oc[mt][pxg][1] * is1;
                ob1[w+1] = oc[mt][pxg][3] * is1;
            }
        }
    }
}

// ---------------- launch ------------------------------------------------------
extern "C" void kernel_launch(void* const* d_in, const int* in_sizes, int n_in,
                              void* d_out, int out_size)
{
    (void)in_sizes; (void)n_in; (void)out_size;
    const float* img  = (const float*)d_in[0];
    const float* wimg = (const float*)d_in[1];
    const float* wc   = (const float*)d_in[2];
    const float* gg   = (const float*)d_in[3];
    const float* bb   = (const float*)d_in[4];
    const float* mm   = (const float*)d_in[5];
    const float* vv   = (const float*)d_in[6];
    float* out = (float*)d_out;

    static int attr_set = 0;
    if (!attr_set) {
        cudaFuncSetAttribute(attn_kernel,
                             cudaFuncAttributeMaxDynamicSharedMemorySize, SMEM2_BYTES);
        cudaFuncSetAttribute(qkv_kernel,
                             cudaFuncAttributeMaxDynamicSharedMemorySize, QKV_SMEM);
        attr_set = 1;
    }

    prep_kernel<<<(PREP_N + 255)/256, 256>>>(wc, gg, bb, mm, vv);

    dim3 qgrid(HW_/128, BN_);   // 175 x 6
    qkv_kernel<<<qgrid, 128, QKV_SMEM>>>(img, wimg);

    dim3 agrid((W_ + 15)/16, H_/8, BN_);   // 13 x 14 x 6
    attn_kernel<<<agrid, 256, SMEM2_BYTES>>>(out);
}